// round 14
// baseline (speedup 1.0000x reference)
#include <cuda_runtime.h>
#include <cuda_fp16.h>
#include <math.h>
#include <stdint.h>

// ---------------- problem constants ----------------
#define BB    16
#define LL    1024
#define NN    1026          // L + 2
#define HIDD  512
#define NHEAD 4
#define DH    128
#define NLAY  2
#define WINR  5
#define FF    2048          // 4*HID
#define SLOPE 0.2f
#define LNEPS 1e-5f
#define JSPLIT 4

// ---------------- scratch (device globals; no allocation allowed) ----------------
__device__ float d_nodes[(size_t)BB * NN * HIDD];
__device__ float d_sq   [(size_t)BB * NHEAD * NN];
__device__ float d_sk   [(size_t)BB * NHEAD * NN];
__device__ float d_midgl[(size_t)2 * BB * FF];     // [g | l]
__device__ float d_ygl  [(size_t)2 * BB * HIDD];   // [g | l]
__device__ float d_glpart[(size_t)JSPLIT * BB * 2 * HIDD];

// fp16 buffers
__device__ __half d_proj [(size_t)(BB * NN) * HIDD];
__device__ __half d_Aproj[(size_t)(BB * NN) * HIDD];
__device__ __half d_Atok [(size_t)(BB * LL) * HIDD];
__device__ __half d_Amid [(size_t)(BB * LL) * FF];
__device__ __half d_ffnh [(size_t)(BB * LL) * HIDD];  // FFN2 out (fp16)
__device__ __half d_Bw   [(size_t)NLAY * HIDD * HIDD];
__device__ __half d_B1   [(size_t)FF   * HIDD];
__device__ __half d_B2   [(size_t)HIDD * FF];

// ---------------- helpers ----------------
__device__ __forceinline__ float gelu_exact(float x) {
    return 0.5f * x * (1.0f + erff(x * 0.70710678118654752f));
}
__device__ __forceinline__ uint32_t smem_u32(const void* p) {
    uint32_t a;
    asm("{ .reg .u64 t; cvta.to.shared.u64 t, %1; cvt.u32.u64 %0, t; }" : "=r"(a) : "l"(p));
    return a;
}
__device__ __forceinline__ void cpa16(uint32_t dst, const void* src, bool pred) {
    int sz = pred ? 16 : 0;
    asm volatile("cp.async.cg.shared.global [%0], [%1], 16, %2;" :: "r"(dst), "l"(src), "r"(sz));
}
__device__ __forceinline__ void ldm_x4(uint32_t* r, uint32_t addr) {
    asm volatile("ldmatrix.sync.aligned.m8n8.x4.shared.b16 {%0, %1, %2, %3}, [%4];"
                 : "=r"(r[0]), "=r"(r[1]), "=r"(r[2]), "=r"(r[3]) : "r"(addr));
}
__device__ __forceinline__ void mma16816(float* d, const uint32_t* a, const uint32_t* b) {
    asm volatile("mma.sync.aligned.m16n8k16.row.col.f32.f16.f16.f32 "
                 "{%0, %1, %2, %3}, {%4, %5, %6, %7}, {%8, %9}, {%0, %1, %2, %3};"
                 : "+f"(d[0]), "+f"(d[1]), "+f"(d[2]), "+f"(d[3])
                 : "r"(a[0]), "r"(a[1]), "r"(a[2]), "r"(a[3]), "r"(b[0]), "r"(b[1]));
}
__device__ __forceinline__ uint32_t sw128(uint32_t off) {
    return off ^ ((off >> 3) & 0x70);
}

// ---------------- HMMA fp16 GEMM, 3-stage pipeline ----------------
// mode 0: Cf = acc ; mode 1: Cf = acc + bias ;
// mode 2: Cb[m*K0+n] = fp16(gelu(acc+bias))
// mode 3: Cb[m*K0+n] = fp16(acc) AND fused sq/sk emit (grid.x==NHEAD)
// mode 4: Cb[m*K0+n] = fp16(acc+bias)
#define GM_SMEM (98304)
__global__ void __launch_bounds__(256, 2)
mma_gemm_kernel(const __half* __restrict__ A,
                const __half* __restrict__ B,
                const float* __restrict__ bias,
                float* __restrict__ Cf,
                __half* __restrict__ Cb,
                int M, int Kt, int ldk, int ldc, int mode, int K0,
                const float* __restrict__ gq,
                float* __restrict__ sqo,
                float* __restrict__ sko) {
    extern __shared__ __align__(1024) char dynsm[];
    const uint32_t sbase = smem_u32(dynsm);
    const int tid  = threadIdx.x;
    const int lane = tid & 31;
    const int wid  = tid >> 5;
    const int wm   = wid & 1;
    const int wn   = wid >> 1;
    const int m0 = blockIdx.y * 128;
    const int n0 = blockIdx.x * 128;

    const char* Ag = (const char*)A;
    const char* Bg = (const char*)B;
    const size_t ldkb = (size_t)ldk * 2;

    float acc[4][4][4];
#pragma unroll
    for (int i = 0; i < 4; i++)
#pragma unroll
        for (int j = 0; j < 4; j++)
#pragma unroll
            for (int c = 0; c < 4; c++) acc[i][j][c] = 0.f;

    const int lrow[4] = { (0 * 256 + tid) >> 3, (1 * 256 + tid) >> 3,
                          (2 * 256 + tid) >> 3, (3 * 256 + tid) >> 3 };
    const int lch = tid & 7;

    auto load_tile = [&](int buf, int t) {
        size_t kb = (size_t)t * 128 + lch * 16;
        uint32_t sA = sbase + buf * 16384u;
        uint32_t sB = sbase + 49152u + buf * 16384u;
#pragma unroll
        for (int i = 0; i < 4; i++) {
            int row = lrow[i];
            uint32_t off = (uint32_t)(row * 128 + lch * 16);
            int m = m0 + row;
            cpa16(sA + sw128(off), Ag + (size_t)(m < M ? m : 0) * ldkb + kb, m < M);
        }
#pragma unroll
        for (int i = 0; i < 4; i++) {
            int row = lrow[i];
            uint32_t off = (uint32_t)(row * 128 + lch * 16);
            cpa16(sB + sw128(off), Bg + (size_t)(n0 + row) * ldkb + kb, true);
        }
        asm volatile("cp.async.commit_group;" ::: "memory");
    };

    auto compute_tile = [&](int buf) {
        uint32_t sA = sbase + buf * 16384u;
        uint32_t sB = sbase + 49152u + buf * 16384u;
        const int r15 = lane & 15;
        const int kh16 = (lane & 16);
#pragma unroll
        for (int ks = 0; ks < 4; ks++) {
            uint32_t kb = ks * 32 + kh16;
            uint32_t a[4][4];
#pragma unroll
            for (int tm = 0; tm < 4; tm++) {
                uint32_t off = (uint32_t)((wm * 64 + tm * 16 + r15) * 128) + kb;
                ldm_x4(a[tm], sA + sw128(off));
            }
            uint32_t b[4][2];
#pragma unroll
            for (int p = 0; p < 2; p++) {
                uint32_t r[4];
                uint32_t off = (uint32_t)((wn * 32 + p * 16 + r15) * 128) + kb;
                ldm_x4(r, sB + sw128(off));
                b[2 * p + 0][0] = r[0]; b[2 * p + 1][0] = r[1];
                b[2 * p + 0][1] = r[2]; b[2 * p + 1][1] = r[3];
            }
#pragma unroll
            for (int tm = 0; tm < 4; tm++)
#pragma unroll
                for (int tn = 0; tn < 4; tn++)
                    mma16816(acc[tm][tn], a[tm], b[tn]);
        }
    };

    load_tile(0, 0);
    load_tile(1, 1);
    int buf = 0;
    for (int t = 0; t < Kt; t++) {
        asm volatile("cp.async.wait_group 1;" ::: "memory");
        __syncthreads();
        if (t + 2 < Kt) {
            int nb = buf + 2; if (nb >= 3) nb -= 3;
            load_tile(nb, t + 2);
        } else {
            asm volatile("cp.async.commit_group;" ::: "memory");
        }
        compute_tile(buf);
        if (++buf == 3) buf = 0;
    }

    const int rbase = lane >> 2;
    const int cbase = 2 * (lane & 3);

    float a1v[4][2], a2v[4][2];
    if (mode == 3) {
        const float* ah = gq + blockIdx.x * (2 * DH);
#pragma unroll
        for (int tn = 0; tn < 4; tn++) {
            int c0 = wn * 32 + tn * 8 + cbase;
            a1v[tn][0] = ah[c0];       a1v[tn][1] = ah[c0 + 1];
            a2v[tn][0] = ah[DH + c0];  a2v[tn][1] = ah[DH + c0 + 1];
        }
    }
    float p1[4][2], p2[4][2];
#pragma unroll
    for (int tm = 0; tm < 4; tm++) { p1[tm][0] = p1[tm][1] = p2[tm][0] = p2[tm][1] = 0.f; }

#pragma unroll
    for (int tm = 0; tm < 4; tm++) {
#pragma unroll
        for (int half = 0; half < 2; half++) {
            int m = m0 + wm * 64 + tm * 16 + rbase + half * 8;
            if (m >= M) continue;
#pragma unroll
            for (int tn = 0; tn < 4; tn++) {
                int n = n0 + wn * 32 + tn * 8 + cbase;
                float v0 = acc[tm][tn][half * 2 + 0];
                float v1 = acc[tm][tn][half * 2 + 1];
                if (mode == 2) {
                    __half2 hv;
                    hv.x = __float2half_rn(gelu_exact(v0 + bias[n]));
                    hv.y = __float2half_rn(gelu_exact(v1 + bias[n + 1]));
                    *(__half2*)(Cb + (size_t)m * K0 + n) = hv;
                } else if (mode == 3) {
                    __half2 hv;
                    hv.x = __float2half_rn(v0);
                    hv.y = __float2half_rn(v1);
                    *(__half2*)(Cb + (size_t)m * K0 + n) = hv;
                    p1[tm][half] += v0 * a1v[tn][0] + v1 * a1v[tn][1];
                    p2[tm][half] += v0 * a2v[tn][0] + v1 * a2v[tn][1];
                } else if (mode == 4) {
                    __half2 hv;
                    hv.x = __float2half_rn(v0 + bias[n]);
                    hv.y = __float2half_rn(v1 + bias[n + 1]);
                    *(__half2*)(Cb + (size_t)m * K0 + n) = hv;
                } else {
                    if (mode == 1) { v0 += bias[n]; v1 += bias[n + 1]; }
                    float2 o; o.x = v0; o.y = v1;
                    *(float2*)(Cf + (size_t)m * ldc + n) = o;
                }
            }
        }
    }

    if (mode == 3) {
        __syncthreads();
        float* red1 = (float*)dynsm;
        float* red2 = red1 + 128 * 16;
        int slot = wn * 4 + (lane & 3);
#pragma unroll
        for (int tm = 0; tm < 4; tm++)
#pragma unroll
            for (int half = 0; half < 2; half++) {
                int rb = wm * 64 + tm * 16 + rbase + half * 8;
                red1[rb * 16 + slot] = p1[tm][half];
                red2[rb * 16 + slot] = p2[tm][half];
            }
        __syncthreads();
        if (tid < 128) {
            int m = m0 + tid;
            if (m < M) {
                float s1 = 0.f, s2 = 0.f;
#pragma unroll
                for (int i = 0; i < 16; i++) {
                    s1 += red1[tid * 16 + i];
                    s2 += red2[tid * 16 + i];
                }
                int b = m / NN, n = m % NN;
                size_t o = ((size_t)b * NHEAD + blockIdx.x) * NN + n;
                sqo[o] = s1;
                sko[o] = s2;
            }
        }
    }
}

// ---------------- weight conversion ----------------
// smem-tiled transpose-convert: in fp32 (K x N) -> out fp16 (N x K). 32x32 tiles.
__global__ void splitT1_kernel(const float* __restrict__ in,
                               __half* __restrict__ out,
                               int K, int N) {
    __shared__ float tile[32][33];
    int nb = blockIdx.x * 32;
    int kb = blockIdx.y * 32;
    int tx = threadIdx.x;
    int ty = threadIdx.y;
#pragma unroll
    for (int i = 0; i < 4; i++) {
        int k = kb + ty + i * 8;
        tile[ty + i * 8][tx] = in[(size_t)k * N + nb + tx];
    }
    __syncthreads();
#pragma unroll
    for (int i = 0; i < 4; i++) {
        int n = nb + ty + i * 8;
        out[(size_t)n * K + kb + tx] = __float2half_rn(tile[tx][ty + i * 8]);
    }
}
__global__ void castW_kernel(const float* __restrict__ in,
                             __half* __restrict__ out, int total) {
    int idx = blockIdx.x * 256 + threadIdx.x;
    if (idx >= total) return;
    out[idx] = __float2half_rn(in[idx]);
}

// ---------------- build nodes ----------------
__global__ void build_nodes_kernel(const float* __restrict__ g,
                                   const float* __restrict__ t,
                                   const float* __restrict__ l,
                                   float* __restrict__ nodes,
                                   __half* __restrict__ aout) {
    int idx = blockIdx.x * 256 + threadIdx.x;
    int total = BB * NN * HIDD;
    if (idx >= total) return;
    int d = idx % HIDD;
    int r = (idx / HIDD) % NN;
    int b = idx / (HIDD * NN);
    float v;
    if (r == 0)            v = g[b * HIDD + d];
    else if (r == NN - 1)  v = l[b * HIDD + d];
    else                   v = t[((size_t)b * LL + (r - 1)) * HIDD + d];
    nodes[idx] = v;
    aout[idx] = __float2half_rn(v);
}

// ---------------- batched g/l fp32 SGEMM ----------------
#define BM_ 64
#define BN_ 64
#define BK_ 16
__global__ void sgemm_gl_kernel(const float* __restrict__ A0,
                                const float* __restrict__ A1,
                                const float* __restrict__ B0,
                                const float* __restrict__ B1,
                                const float* __restrict__ bias0,
                                const float* __restrict__ bias1,
                                float* __restrict__ C0,
                                float* __restrict__ C1,
                                int M, int Ncol, int K, int act,
                                int astride, int arb0, int arb1) {
    const int z = blockIdx.z;
    const float* A   = z ? A1 : A0;
    const float* Bm  = z ? B1 : B0;
    const float* bias = z ? bias1 : bias0;
    float* C = z ? C1 : C0;
    const int arb = z ? arb1 : arb0;

    __shared__ float As[BM_][BK_];
    __shared__ float Bs[BK_][BN_];
    const int tid = threadIdx.x;
    const int tm = tid >> 4;
    const int tn = tid & 15;
    const int row0 = blockIdx.y * BM_;
    const int col0 = blockIdx.x * BN_;
    float acc[4][4] = {};
    const int ar = tid >> 2;
    const int ak = (tid & 3) << 2;
    const float* Arow = nullptr;
    {
        int mm = row0 + ar;
        if (mm < M) Arow = A + (size_t)(mm * astride + arb) * K;
    }
    const int bk0 = tid >> 4;
    const int bn0 = (tid & 15) << 2;
    for (int k0 = 0; k0 < K; k0 += BK_) {
        float4 av = make_float4(0.f, 0.f, 0.f, 0.f);
        if (Arow) av = *(const float4*)(Arow + k0 + ak);
        *(float4*)(&As[ar][ak]) = av;
        float4 bv = *(const float4*)(Bm + (size_t)(k0 + bk0) * Ncol + col0 + bn0);
        *(float4*)(&Bs[bk0][bn0]) = bv;
        __syncthreads();
#pragma unroll
        for (int kk = 0; kk < BK_; kk++) {
            float a0 = As[tm * 4 + 0][kk];
            float a1 = As[tm * 4 + 1][kk];
            float a2 = As[tm * 4 + 2][kk];
            float a3 = As[tm * 4 + 3][kk];
            float4 bv2 = *(const float4*)(&Bs[kk][tn * 4]);
            acc[0][0] += a0 * bv2.x; acc[0][1] += a0 * bv2.y; acc[0][2] += a0 * bv2.z; acc[0][3] += a0 * bv2.w;
            acc[1][0] += a1 * bv2.x; acc[1][1] += a1 * bv2.y; acc[1][2] += a1 * bv2.z; acc[1][3] += a1 * bv2.w;
            acc[2][0] += a2 * bv2.x; acc[2][1] += a2 * bv2.y; acc[2][2] += a2 * bv2.z; acc[2][3] += a2 * bv2.w;
            acc[3][0] += a3 * bv2.x; acc[3][1] += a3 * bv2.y; acc[3][2] += a3 * bv2.z; acc[3][3] += a3 * bv2.w;
        }
        __syncthreads();
    }
    int n = col0 + tn * 4;
    float4 bsv = make_float4(0.f, 0.f, 0.f, 0.f);
    if (bias) bsv = *(const float4*)(bias + n);
#pragma unroll
    for (int i = 0; i < 4; i++) {
        int mm = row0 + tm * 4 + i;
        if (mm >= M) continue;
        float4 v = make_float4(acc[i][0] + bsv.x, acc[i][1] + bsv.y,
                               acc[i][2] + bsv.z, acc[i][3] + bsv.w);
        if (act == 1) {
            v.x = gelu_exact(v.x); v.y = gelu_exact(v.y);
            v.z = gelu_exact(v.z); v.w = gelu_exact(v.w);
        }
        *(float4*)(C + (size_t)mm * Ncol + n) = v;
    }
}

// ---------------- fused token attention + elu + residual + LN + fp16 out ----------------
#define QB 8
#define UMAX 20
__global__ void __launch_bounds__(512)
token_attn_ln_kernel(const __half* __restrict__ P,
                     const float* __restrict__ sq,
                     const float* __restrict__ sk,
                     const float* __restrict__ am,
                     const int* __restrict__ last,
                     float* __restrict__ nodes,
                     const float* __restrict__ gamma,
                     const float* __restrict__ beta,
                     __half* __restrict__ aout,
                     int aidx_mode) {
    int b  = blockIdx.y;
    int i0 = blockIdx.x * QB;
    int tid = threadIdx.x;

    __shared__ __align__(16) float rows[UMAX][HIDD];
    __shared__ float sks[NHEAD][UMAX];
    __shared__ float w[QB][NHEAD][13];
    __shared__ int   qk[QB][13];
    __shared__ int   qnk[QB];
    __shared__ int   ukeys[UMAX];
    __shared__ int   unk_s;
    __shared__ float wsum[16], wsq[16];
    __shared__ float lnm[QB], lnr[QB];

    if (tid == 0) {
        int lo = i0 - WINR < 0 ? 0 : i0 - WINR;
        int hi = i0 + QB - 1 + WINR;
        if (hi > LL - 1) hi = LL - 1;
        int slot_t[2 * WINR + QB];
        int un = 0;
        ukeys[un++] = 0;
        for (int t = lo; t <= hi; t++) {
            if (am[b * LL + t] > 0.f) { ukeys[un] = 1 + t; slot_t[t - lo] = un; un++; }
            else slot_t[t - lo] = -1;
        }
        int lastv = last[b];
        int locslot = -1;
        if (i0 + QB - 1 >= lastv) { locslot = un; ukeys[un++] = NN - 1; }
        unk_s = un;
        for (int q = 0; q < QB; q++) {
            int i = i0 + q;
            int nk = 0;
            qk[q][nk++] = 0;
            int l2 = i - WINR < 0 ? 0 : i - WINR;
            int h2 = i + WINR > LL - 1 ? LL - 1 : i + WINR;
            for (int t = l2; t <= h2; t++) {
                int s = slot_t[t - lo];
                if (s >= 0) qk[q][nk++] = s;
            }
            if (i >= lastv) qk[q][nk++] = locslot;
            qnk[q] = nk;
        }
    }
    __syncthreads();
    int un = unk_s;

    {
        int rsub = tid >> 7;
        int d4 = (tid & 127) * 4;
        const __half* Pb = P + (size_t)b * NN * HIDD;
        for (int r = rsub; r < un; r += 4) {
            const __half* src = Pb + (size_t)ukeys[r] * HIDD + d4;
            __half2 h01 = *(const __half2*)(src);
            __half2 h23 = *(const __half2*)(src + 2);
            float2 f01 = __half22float2(h01);
            float2 f23 = __half22float2(h23);
            rows[r][d4 + 0] = f01.x; rows[r][d4 + 1] = f01.y;
            rows[r][d4 + 2] = f23.x; rows[r][d4 + 3] = f23.y;
        }
    }
    if (tid < NHEAD * UMAX) {
        int h = tid / UMAX, kidx = tid % UMAX;
        if (kidx < un)
            sks[h][kidx] = sk[((size_t)b * NHEAD + h) * NN + ukeys[kidx]];
    }
    __syncthreads();

    if (tid < QB * NHEAD) {
        int q = tid >> 2, h = tid & 3;
        int nk = qnk[q];
        float sqv = sq[((size_t)b * NHEAD + h) * NN + 1 + i0 + q];
        float sc[13];
        float mx = -3e38f;
        for (int jj = 0; jj < nk; jj++) {
            float s = sqv + sks[h][qk[q][jj]];
            s = s >= 0.f ? s : SLOPE * s;
            sc[jj] = s;
            mx = fmaxf(mx, s);
        }
        float sum = 0.f;
        for (int jj = 0; jj < nk; jj++) {
            float e = expf(sc[jj] - mx);
            w[q][h][jj] = e;
            sum += e;
        }
        float inv = 1.f / sum;
        for (int jj = 0; jj < nk; jj++) w[q][h][jj] *= inv;
    }
    __syncthreads();

    int d = tid;
    int h = d >> 7;
    float v[QB];
#pragma unroll
    for (int q = 0; q < QB; q++) {
        int nk = qnk[q];
        float acc = 0.f;
        for (int jj = 0; jj < nk; jj++)
            acc += w[q][h][jj] * rows[qk[q][jj]][d];
        acc = acc > 0.f ? acc : expm1f(acc);
        v[q] = acc + nodes[((size_t)b * NN + 1 + i0 + q) * HIDD + d];
    }
    __syncthreads();

#pragma unroll
    for (int q = 0; q < QB; q++) rows[q][d] = v[q];
    __syncthreads();

    {
        int g = tid >> 6;
        int t = tid & 63;
        float s = 0.f, s2 = 0.f;
#pragma unroll
        for (int j = 0; j < 8; j++) {
            float x = rows[g][t + 64 * j];
            s += x; s2 += x * x;
        }
#pragma unroll
        for (int o = 16; o > 0; o >>= 1) {
            s  += __shfl_down_sync(0xffffffffu, s,  o);
            s2 += __shfl_down_sync(0xffffffffu, s2, o);
        }
        int wix = tid >> 5;
        if ((tid & 31) == 0) { wsum[wix] = s; wsq[wix] = s2; }
        __syncthreads();
        if (t == 0) {
            float ts = wsum[2 * g] + wsum[2 * g + 1];
            float tq = wsq[2 * g] + wsq[2 * g + 1];
            float mean = ts * (1.f / HIDD);
            float var = tq * (1.f / HIDD) - mean * mean;
            lnm[g] = mean;
            lnr[g] = rsqrtf(var + LNEPS);
        }
        __syncthreads();
    }

    float gmv = gamma[d], btv = beta[d];
#pragma unroll
    for (int q = 0; q < QB; q++) {
        float y = (v[q] - lnm[q]) * lnr[q] * gmv + btv;
        nodes[((size_t)b * NN + 1 + i0 + q) * HIDD + d] = y;
        size_t orow = (aidx_mode == 0) ? ((size_t)b * NN + 1 + i0 + q)
                                       : ((size_t)b * LL + i0 + q);
        aout[orow * HIDD + d] = __float2half_rn(y);
    }
}

// ---------------- dense global/local attention, J-split partials ----------------
__global__ void __launch_bounds__(512)
gl_attn_part_kernel(const __half* __restrict__ P,
                    const float* __restrict__ sq,
                    const float* __restrict__ sk,
                    const int* __restrict__ last,
                    float* __restrict__ part) {
    int b = blockIdx.y;
    int which = blockIdx.x & 1;
    int js = blockIdx.x >> 1;
    int qn = which == 0 ? 0 : NN - 1;
    int tid = threadIdx.x;
    __shared__ float ssm[NHEAD][NN];
    __shared__ float red[512];
    int lastv = last[b];
    int h = tid >> 7;
    int r = tid & 127;
    float sqv = sq[((size_t)b * NHEAD + h) * NN + qn];
    const float* skh = sk + ((size_t)b * NHEAD + h) * NN;
    float mx = -3e38f;
    for (int j = r; j < NN; j += 128) {
        bool ok = (which == 0) || (j == 0) || (j == NN - 1) ||
                  (j >= lastv + 1 && j <= LL);
        float s;
        if (ok) {
            s = sqv + skh[j];
            s = s >= 0.f ? s : SLOPE * s;
        } else s = -1e30f;
        ssm[h][j] = s;
        mx = fmaxf(mx, s);
    }
    red[tid] = mx;
    __syncthreads();
    for (int s = 64; s > 0; s >>= 1) {
        if (r < s) red[tid] = fmaxf(red[tid], red[tid + s]);
        __syncthreads();
    }
    float mhead = red[h * 128];
    __syncthreads();
    float sum = 0.f;
    for (int j = r; j < NN; j += 128) {
        float e = expf(ssm[h][j] - mhead);
        ssm[h][j] = e;
        sum += e;
    }
    red[tid] = sum;
    __syncthreads();
    for (int s = 64; s > 0; s >>= 1) {
        if (r < s) red[tid] += red[tid + s];
        __syncthreads();
    }
    float inv = 1.f / red[h * 128];
    __syncthreads();
    for (int j = r; j < NN; j += 128) ssm[h][j] *= inv;
    __syncthreads();

    const int CH = (NN + JSPLIT - 1) / JSPLIT;
    int jlo = js * CH;
    int jhi = jlo + CH; if (jhi > NN) jhi = NN;
    int d = tid;
    int hh = d >> 7;
    const __half* Pb = P + (size_t)b * NN * HIDD + d;
    float a0 = 0.f, a1 = 0.f, a2 = 0.f, a3 = 0.f;
    float a4 = 0.f, a5 = 0.f, a6 = 0.f, a7 = 0.f;
    int j = jlo;
    for (; j + 7 < jhi; j += 8) {
        a0 += ssm[hh][j + 0] * __half2float(Pb[(size_t)(j + 0) * HIDD]);
        a1 += ssm[hh][j + 1] * __half2float(Pb[(size_t)(j + 1) * HIDD]);
        a2 += ssm[hh][j + 2] * __half2float(Pb[(size_t)(j + 2) * HIDD]);
        a3 += ssm[hh][j + 3] * __half2float(Pb[(size_t)(j + 3) * HIDD]);
        a4 += ssm[hh][j + 4] * __half2float(Pb[(size_t)(j + 4) * HIDD]);
        a5 += ssm[hh][j + 5] * __half2float(Pb[(size_t)(j + 5) * HIDD]);
        a6 += ssm[hh][j + 6] * __half2float(Pb[(size_t)(j + 6) * HIDD]);
        a7 += ssm[hh][j + 7] * __half2float(Pb[(size_t)(j + 7) * HIDD]);
    }
    for (; j < jhi; j++) a0 += ssm[hh][j] * __half2float(Pb[(size_t)j * HIDD]);
    part[(((size_t)js * BB + b) * 2 + which) * HIDD + d] =
        ((a0 + a1) + (a2 + a3)) + ((a4 + a5) + (a6 + a7));
}

// ---------------- fused gl reduce + elu + residual + LN + optional fp16 out ----------------
__global__ void __launch_bounds__(512)
gl_ln_kernel(const float* __restrict__ part,
             float* __restrict__ nodes,
             const float* __restrict__ gamma,
             const float* __restrict__ beta,
             __half* __restrict__ aout,
             int write_a) {
    int row = blockIdx.x;
    int b = row >> 1;
    int which = row & 1;
    int qn = which == 0 ? 0 : NN - 1;
    int d = threadIdx.x;
    float s = 0.f;
#pragma unroll
    for (int js = 0; js < JSPLIT; js++)
        s += part[(((size_t)js * BB + b) * 2 + which) * HIDD + d];
    s = s > 0.f ? s : expm1f(s);
    size_t nrow = (size_t)b * NN + qn;
    float x = nodes[nrow * HIDD + d] + s;

    __shared__ float red[2];
    __shared__ float wsum[16], wsq[16];
    float p1 = x, p2 = x * x;
#pragma unroll
    for (int o = 16; o > 0; o >>= 1) {
        p1 += __shfl_down_sync(0xffffffffu, p1, o);
        p2 += __shfl_down_sync(0xffffffffu, p2, o);
    }
    int wix = d >> 5;
    if ((d & 31) == 0) { wsum[wix] = p1; wsq[wix] = p2; }
    __syncthreads();
    if (d == 0) {
        float ts = 0.f, tq = 0.f;
#pragma unroll
        for (int i = 0; i < 16; i++) { ts += wsum[i]; tq += wsq[i]; }
        float mean = ts * (1.f / HIDD);
        float var = tq * (1.f / HIDD) - mean * mean;
        red[0] = mean;
        red[1] = rsqrtf(var + LNEPS);
    }
    __syncthreads();
    float y = (x - red[0]) * red[1] * gamma[d] + beta[d];
    nodes[nrow * HIDD + d] = y;
    if (write_a) aout[nrow * HIDD + d] = __float2half_rn(y);
}

// ---------------- out = LN(nodes_row + y_row), y fp16, single-pass ----------------
__global__ void final_ln_kernel(const float* __restrict__ nodes,
                                int rpb, int bstride, int rbase,
                                const __half* __restrict__ y,
                                const float* __restrict__ gamma,
                                const float* __restrict__ beta,
                                float* __restrict__ out) {
    int row = blockIdx.x;
    int tid = threadIdx.x;               // 256
    int pr = (row / rpb) * bstride + rbase + (row % rpb);
    size_t nb = (size_t)pr * HIDD;
    size_t yb = (size_t)row * HIDD;
    float x0 = nodes[nb + tid]       + __half2float(y[yb + tid]);
    float x1 = nodes[nb + tid + 256] + __half2float(y[yb + tid + 256]);
    __shared__ float wsum[8], wsq[8], mv[2];
    float s = x0 + x1;
    float s2 = x0 * x0 + x1 * x1;
#pragma unroll
    for (int o = 16; o > 0; o >>= 1) {
        s  += __shfl_down_sync(0xffffffffu, s,  o);
        s2 += __shfl_down_sync(0xffffffffu, s2, o);
    }
    int wix = tid >> 5;
    if ((tid & 31) == 0) { wsum[wix] = s; wsq[wix] = s2; }
    __syncthreads();
    if (tid == 0) {
        float ts = 0.f, tq = 0.f;
#pragma unroll
        for (int i = 0; i < 8; i++) { ts += wsum[i]; tq += wsq[i]; }
        float mean = ts * (1.f / HIDD);
        float var = tq * (1.f / HIDD) - mean * mean;
        mv[0] = mean;
        mv[1] = rsqrtf(var + LNEPS);
    }
    __syncthreads();
    float mean = mv[0], rstd = mv[1];
    out[yb + tid]       = (x0 - mean) * rstd * gamma[tid] + beta[tid];
    out[yb + tid + 256] = (x1 - mean) * rstd * gamma[tid + 256] + beta[tid + 256];
}

// ---------------- batched g/l final LN (32 blocks) ----------------
__global__ void gl_final_ln_kernel(const float* __restrict__ nodes,
                                   const float* __restrict__ ygl,
                                   const float* __restrict__ og,
                                   const float* __restrict__ ob,
                                   float* __restrict__ out_g,
                                   float* __restrict__ out_l) {
    int idx = blockIdx.x;
    int which = idx >> 4;
    int b = idx & 15;
    int tid = threadIdx.x;
    int qn = which == 0 ? 0 : NN - 1;
    const float* gamma = og + (which == 0 ? 0 : 2 * HIDD);
    const float* beta  = ob + (which == 0 ? 0 : 2 * HIDD);
    float* out = (which == 0 ? out_g : out_l) + (size_t)b * HIDD;
    size_t nb = ((size_t)b * NN + qn) * HIDD;
    size_t yb = ((size_t)which * BB + b) * HIDD;
    float x0 = nodes[nb + tid]       + ygl[yb + tid];
    float x1 = nodes[nb + tid + 256] + ygl[yb + tid + 256];
    __shared__ float wsum[8], wsq[8], mv[2];
    float s = x0 + x1;
    float s2 = x0 * x0 + x1 * x1;
#pragma unroll
    for (int o = 16; o > 0; o >>= 1) {
        s  += __shfl_down_sync(0xffffffffu, s,  o);
        s2 += __shfl_down_sync(0xffffffffu, s2, o);
    }
    int wix = tid >> 5;
    if ((tid & 31) == 0) { wsum[wix] = s; wsq[wix] = s2; }
    __syncthreads();
    if (tid == 0) {
        float ts = 0.f, tq = 0.f;
#pragma unroll
        for (int i = 0; i < 8; i++) { ts += wsum[i]; tq += wsq[i]; }
        float mean = ts * (1.f / HIDD);
        float var = tq * (1.f / HIDD) - mean * mean;
        mv[0] = mean;
        mv[1] = rsqrtf(var + LNEPS);
    }
    __syncthreads();
    float mean = mv[0], rstd = mv[1];
    out[tid]       = (x0 - mean) * rstd * gamma[tid] + beta[tid];
    out[tid + 256] = (x1 - mean) * rstd * gamma[tid + 256] + beta[tid + 256];
}

// ---------------- orchestration ----------------
extern "C" void kernel_launch(void* const* d_in, const int* in_sizes, int n_in,
                              void* d_out, int out_size) {
    const float* ge   = (const float*)d_in[0];
    const float* te   = (const float*)d_in[1];
    const float* le   = (const float*)d_in[2];
    const float* am   = (const float*)d_in[3];
    const int*   last = (const int*)  d_in[4];
    const float* W    = (const float*)d_in[5];
    const float* ga   = (const float*)d_in[6];
    const float* lng  = (const float*)d_in[7];
    const float* lnb  = (const float*)d_in[8];
    const float* w1   = (const float*)d_in[9];
    const float* b1   = (const float*)d_in[10];
    const float* w2   = (const float*)d_in[11];
    const float* b2   = (const float*)d_in[12];
    const float* og   = (const float*)d_in[13];
    const float* ob   = (const float*)d_in[14];
    float* out = (float*)d_out;

    float *nodes, *sqp, *skp, *midgl, *ygl, *glpart;
    __half *proj, *Aproj, *Atok, *Amid, *ffnh, *Bw, *B1, *B2;
    cudaGetSymbolAddress((void**)&nodes, d_nodes);
    cudaGetSymbolAddress((void**)&sqp,   d_sq);
    cudaGetSymbolAddress((void**)&skp,   d_sk);
    cudaGetSymbolAddress((void**)&midgl, d_midgl);
    cudaGetSymbolAddress((void**)&ygl,   d_ygl);
    cudaGetSymbolAddress((void**)&glpart,d_glpart);
    cudaGetSymbolAddress((void**)&proj,  d_proj);
    cudaGetSymbolAddress((void**)&Aproj, d_Aproj);
    cudaGetSymbolAddress((void**)&Atok,  d_Atok);
    cudaGetSymbolAddress((void**)&Amid,  d_Amid);
    cudaGetSymbolAddress((void**)&ffnh,  d_ffnh);
    cudaGetSymbolAddress((void**)&Bw,    d_Bw);
    cudaGetSymbolAddress((void**)&B1,    d_B1);
    cudaGetSymbolAddress((void**)&B2,    d_B2);

    cudaFuncSetAttribute(mma_gemm_kernel,
                         cudaFuncAttributeMaxDynamicSharedMemorySize, GM_SMEM);

    const int MN = BB * NN;   // 16416
    const int MT = BB * LL;   // 16384

    build_nodes_kernel<<<(BB * NN * HIDD + 255) / 256, 256>>>(ge, te, le, nodes, Aproj);

    castW_kernel<<<(NLAY * HIDD * HIDD + 255) / 256, 256>>>(W, Bw, NLAY * HIDD * HIDD);
    splitT1_kernel<<<dim3(FF / 32, HIDD / 32), dim3(32, 8)>>>(w1 + (size_t)1 * HIDD * FF, B1, HIDD, FF);
    splitT1_kernel<<<dim3(HIDD / 32, FF / 32), dim3(32, 8)>>>(w2 + (size_t)1 * FF * HIDD, B2, FF, HIDD);

    for (int k = 0; k < NLAY; k++) {
        mma_gemm_kernel<<<dim3(NHEAD, (MN + 127) / 128), 256, GM_SMEM>>>(
            Aproj, Bw + (size_t)k * HIDD * HIDD, nullptr, nullptr, proj,
            MN, 8, HIDD, 0, 3, HIDD,
            ga + (size_t)k * NHEAD * 2 * DH, sqp, skp);
        gl_attn_part_kernel<<<dim3(2 * JSPLIT, BB), 512>>>(proj, sqp, skp, last, glpart);
        if (k == 0) {
            token_attn_ln_kernel<<<dim3(LL / QB, BB), 512>>>(
                proj, sqp, skp, am, last, nodes, lng, lnb, Aproj, 0);
            gl_ln_kernel<<<BB * 2, 512>>>(glpart, nodes, lng, lnb, Aproj, 1);
        } else {
            token_attn_ln_kernel<<<dim3(LL / QB, BB), 512>>>(
                proj, sqp, skp, am, last, nodes, lng + k * HIDD, lnb + k * HIDD, Atok, 1);
            gl_ln_kernel<<<BB * 2, 512>>>(glpart, nodes, lng + k * HIDD, lnb + k * HIDD,
                                          nullptr, 0);
        }
    }

    // token FFN (FFN2 out in fp16, mode 4)
    mma_gemm_kernel<<<dim3(FF / 128, MT / 128), 256, GM_SMEM>>>(
        Atok, B1, b1 + 1 * FF, nullptr, Amid, MT, 8, HIDD, 0, 2, FF,
        nullptr, nullptr, nullptr);
    mma_gemm_kernel<<<dim3(HIDD / 128, MT / 128), 256, GM_SMEM>>>(
        Amid, B2, b2 + 1 * HIDD, nullptr, ffnh, MT, 32, FF, 0, 4, HIDD,
        nullptr, nullptr, nullptr);
    final_ln_kernel<<<MT, 256>>>(nodes, LL, NN, 1, ffnh,
                                 og + 1 * HIDD, ob + 1 * HIDD, out + BB * HIDD);

    // g/l FFN, batched over z
    sgemm_gl_kernel<<<dim3(FF / BN_, 1, 2), 256>>>(
        nodes, nodes,
        w1 + (size_t)0, w1 + (size_t)2 * HIDD * FF,
        b1 + 0, b1 + 2 * FF,
        midgl, midgl + (size_t)BB * FF,
        BB, FF, HIDD, /*gelu*/1, NN, 0, NN - 1);
    sgemm_gl_kernel<<<dim3(HIDD / BN_, 1, 2), 256>>>(
        midgl, midgl + (size_t)BB * FF,
        w2 + (size_t)0, w2 + (size_t)2 * FF * HIDD,
        b2 + 0, b2 + 2 * HIDD,
        ygl, ygl + (size_t)BB * HIDD,
        BB, HIDD, FF, 0, 1, 0, 0);
    gl_final_ln_kernel<<<2 * BB, 256>>>(nodes, ygl, og, ob,
                                        out,
                                        out + BB * HIDD + (size_t)BB * LL * HIDD);
}

// round 15
// speedup vs baseline: 1.0273x; 1.0273x over previous
#include <cuda_runtime.h>
#include <cuda_fp16.h>
#include <math.h>
#include <stdint.h>

// ---------------- problem constants ----------------
#define BB    16
#define LL    1024
#define NN    1026          // L + 2
#define HIDD  512
#define NHEAD 4
#define DH    128
#define NLAY  2
#define WINR  5
#define FF    2048          // 4*HID
#define SLOPE 0.2f
#define LNEPS 1e-5f
#define JSPLIT 4

// ---------------- scratch (device globals; no allocation allowed) ----------------
__device__ float d_nodes[(size_t)BB * NN * HIDD];
__device__ float d_sq   [(size_t)BB * NHEAD * NN];
__device__ float d_sk   [(size_t)BB * NHEAD * NN];
__device__ float d_ffn  [(size_t)BB * LL * HIDD];
__device__ float d_midgl[(size_t)2 * BB * FF];     // [g | l]
__device__ float d_ygl  [(size_t)2 * BB * HIDD];   // [g | l]
__device__ float d_glpart[(size_t)JSPLIT * BB * 2 * HIDD];

// fp16 buffers
__device__ __half d_proj [(size_t)(BB * NN) * HIDD];
__device__ __half d_Aproj[(size_t)(BB * NN) * HIDD];
__device__ __half d_Atok [(size_t)(BB * LL) * HIDD];
__device__ __half d_Amid [(size_t)(BB * LL) * FF];
__device__ __half d_Bw   [(size_t)NLAY * HIDD * HIDD];
__device__ __half d_B1   [(size_t)FF   * HIDD];
__device__ __half d_B2   [(size_t)HIDD * FF];

// ---------------- helpers ----------------
__device__ __forceinline__ float gelu_exact(float x) {
    return 0.5f * x * (1.0f + erff(x * 0.70710678118654752f));
}
__device__ __forceinline__ uint32_t smem_u32(const void* p) {
    uint32_t a;
    asm("{ .reg .u64 t; cvta.to.shared.u64 t, %1; cvt.u32.u64 %0, t; }" : "=r"(a) : "l"(p));
    return a;
}
__device__ __forceinline__ void cpa16(uint32_t dst, const void* src, bool pred) {
    int sz = pred ? 16 : 0;
    asm volatile("cp.async.cg.shared.global [%0], [%1], 16, %2;" :: "r"(dst), "l"(src), "r"(sz));
}
__device__ __forceinline__ void ldm_x4(uint32_t* r, uint32_t addr) {
    asm volatile("ldmatrix.sync.aligned.m8n8.x4.shared.b16 {%0, %1, %2, %3}, [%4];"
                 : "=r"(r[0]), "=r"(r[1]), "=r"(r[2]), "=r"(r[3]) : "r"(addr));
}
__device__ __forceinline__ void mma16816(float* d, const uint32_t* a, const uint32_t* b) {
    asm volatile("mma.sync.aligned.m16n8k16.row.col.f32.f16.f16.f32 "
                 "{%0, %1, %2, %3}, {%4, %5, %6, %7}, {%8, %9}, {%0, %1, %2, %3};"
                 : "+f"(d[0]), "+f"(d[1]), "+f"(d[2]), "+f"(d[3])
                 : "r"(a[0]), "r"(a[1]), "r"(a[2]), "r"(a[3]), "r"(b[0]), "r"(b[1]));
}
__device__ __forceinline__ uint32_t sw128(uint32_t off) {
    return off ^ ((off >> 3) & 0x70);
}

// ---------------- HMMA fp16 GEMM, 3-stage pipeline ----------------
// mode 0: Cf = acc ; mode 1: Cf = acc + bias ;
// mode 2: Cb[m*K0+n] = fp16(gelu(acc+bias))
// mode 3: Cb[m*K0+n] = fp16(acc) AND fused sq/sk emit (grid.x==NHEAD)
#define GM_SMEM (98304)
__global__ void __launch_bounds__(256, 2)
mma_gemm_kernel(const __half* __restrict__ A,
                const __half* __restrict__ B,
                const float* __restrict__ bias,
                float* __restrict__ Cf,
                __half* __restrict__ Cb,
                int M, int Kt, int ldk, int ldc, int mode, int K0,
                const float* __restrict__ gq,
                float* __restrict__ sqo,
                float* __restrict__ sko) {
    extern __shared__ __align__(1024) char dynsm[];
    const uint32_t sbase = smem_u32(dynsm);
    const int tid  = threadIdx.x;
    const int lane = tid & 31;
    const int wid  = tid >> 5;
    const int wm   = wid & 1;
    const int wn   = wid >> 1;
    const int m0 = blockIdx.y * 128;
    const int n0 = blockIdx.x * 128;

    const char* Ag = (const char*)A;
    const char* Bg = (const char*)B;
    const size_t ldkb = (size_t)ldk * 2;

    float acc[4][4][4];
#pragma unroll
    for (int i = 0; i < 4; i++)
#pragma unroll
        for (int j = 0; j < 4; j++)
#pragma unroll
            for (int c = 0; c < 4; c++) acc[i][j][c] = 0.f;

    const int lrow[4] = { (0 * 256 + tid) >> 3, (1 * 256 + tid) >> 3,
                          (2 * 256 + tid) >> 3, (3 * 256 + tid) >> 3 };
    const int lch = tid & 7;

    auto load_tile = [&](int buf, int t) {
        size_t kb = (size_t)t * 128 + lch * 16;
        uint32_t sA = sbase + buf * 16384u;
        uint32_t sB = sbase + 49152u + buf * 16384u;
#pragma unroll
        for (int i = 0; i < 4; i++) {
            int row = lrow[i];
            uint32_t off = (uint32_t)(row * 128 + lch * 16);
            int m = m0 + row;
            cpa16(sA + sw128(off), Ag + (size_t)(m < M ? m : 0) * ldkb + kb, m < M);
        }
#pragma unroll
        for (int i = 0; i < 4; i++) {
            int row = lrow[i];
            uint32_t off = (uint32_t)(row * 128 + lch * 16);
            cpa16(sB + sw128(off), Bg + (size_t)(n0 + row) * ldkb + kb, true);
        }
        asm volatile("cp.async.commit_group;" ::: "memory");
    };

    auto compute_tile = [&](int buf) {
        uint32_t sA = sbase + buf * 16384u;
        uint32_t sB = sbase + 49152u + buf * 16384u;
        const int r15 = lane & 15;
        const int kh16 = (lane & 16);
#pragma unroll
        for (int ks = 0; ks < 4; ks++) {
            uint32_t kb = ks * 32 + kh16;
            uint32_t a[4][4];
#pragma unroll
            for (int tm = 0; tm < 4; tm++) {
                uint32_t off = (uint32_t)((wm * 64 + tm * 16 + r15) * 128) + kb;
                ldm_x4(a[tm], sA + sw128(off));
            }
            uint32_t b[4][2];
#pragma unroll
            for (int p = 0; p < 2; p++) {
                uint32_t r[4];
                uint32_t off = (uint32_t)((wn * 32 + p * 16 + r15) * 128) + kb;
                ldm_x4(r, sB + sw128(off));
                b[2 * p + 0][0] = r[0]; b[2 * p + 1][0] = r[1];
                b[2 * p + 0][1] = r[2]; b[2 * p + 1][1] = r[3];
            }
#pragma unroll
            for (int tm = 0; tm < 4; tm++)
#pragma unroll
                for (int tn = 0; tn < 4; tn++)
                    mma16816(acc[tm][tn], a[tm], b[tn]);
        }
    };

    load_tile(0, 0);
    load_tile(1, 1);
    int buf = 0;
    for (int t = 0; t < Kt; t++) {
        asm volatile("cp.async.wait_group 1;" ::: "memory");
        __syncthreads();
        if (t + 2 < Kt) {
            int nb = buf + 2; if (nb >= 3) nb -= 3;
            load_tile(nb, t + 2);
        } else {
            asm volatile("cp.async.commit_group;" ::: "memory");
        }
        compute_tile(buf);
        if (++buf == 3) buf = 0;
    }

    const int rbase = lane >> 2;
    const int cbase = 2 * (lane & 3);

    float a1v[4][2], a2v[4][2];
    if (mode == 3) {
        const float* ah = gq + blockIdx.x * (2 * DH);
#pragma unroll
        for (int tn = 0; tn < 4; tn++) {
            int c0 = wn * 32 + tn * 8 + cbase;
            a1v[tn][0] = ah[c0];       a1v[tn][1] = ah[c0 + 1];
            a2v[tn][0] = ah[DH + c0];  a2v[tn][1] = ah[DH + c0 + 1];
        }
    }
    float p1[4][2], p2[4][2];
#pragma unroll
    for (int tm = 0; tm < 4; tm++) { p1[tm][0] = p1[tm][1] = p2[tm][0] = p2[tm][1] = 0.f; }

#pragma unroll
    for (int tm = 0; tm < 4; tm++) {
#pragma unroll
        for (int half = 0; half < 2; half++) {
            int m = m0 + wm * 64 + tm * 16 + rbase + half * 8;
            if (m >= M) continue;
#pragma unroll
            for (int tn = 0; tn < 4; tn++) {
                int n = n0 + wn * 32 + tn * 8 + cbase;
                float v0 = acc[tm][tn][half * 2 + 0];
                float v1 = acc[tm][tn][half * 2 + 1];
                if (mode == 2) {
                    __half2 hv;
                    hv.x = __float2half_rn(gelu_exact(v0 + bias[n]));
                    hv.y = __float2half_rn(gelu_exact(v1 + bias[n + 1]));
                    *(__half2*)(Cb + (size_t)m * K0 + n) = hv;
                } else if (mode == 3) {
                    __half2 hv;
                    hv.x = __float2half_rn(v0);
                    hv.y = __float2half_rn(v1);
                    *(__half2*)(Cb + (size_t)m * K0 + n) = hv;
                    p1[tm][half] += v0 * a1v[tn][0] + v1 * a1v[tn][1];
                    p2[tm][half] += v0 * a2v[tn][0] + v1 * a2v[tn][1];
                } else {
                    if (mode == 1) { v0 += bias[n]; v1 += bias[n + 1]; }
                    float2 o; o.x = v0; o.y = v1;
                    *(float2*)(Cf + (size_t)m * ldc + n) = o;
                }
            }
        }
    }

    if (mode == 3) {
        __syncthreads();
        float* red1 = (float*)dynsm;
        float* red2 = red1 + 128 * 16;
        int slot = wn * 4 + (lane & 3);
#pragma unroll
        for (int tm = 0; tm < 4; tm++)
#pragma unroll
            for (int half = 0; half < 2; half++) {
                int rb = wm * 64 + tm * 16 + rbase + half * 8;
                red1[rb * 16 + slot] = p1[tm][half];
                red2[rb * 16 + slot] = p2[tm][half];
            }
        __syncthreads();
        if (tid < 128) {
            int m = m0 + tid;
            if (m < M) {
                float s1 = 0.f, s2 = 0.f;
#pragma unroll
                for (int i = 0; i < 16; i++) {
                    s1 += red1[tid * 16 + i];
                    s2 += red2[tid * 16 + i];
                }
                int b = m / NN, n = m % NN;
                size_t o = ((size_t)b * NHEAD + blockIdx.x) * NN + n;
                sqo[o] = s1;
                sko[o] = s2;
            }
        }
    }
}

// ---------------- weight conversion ----------------
// smem-tiled transpose-convert: in fp32 (K x N) -> out fp16 (N x K). 32x32 tiles.
__global__ void splitT1_kernel(const float* __restrict__ in,
                               __half* __restrict__ out,
                               int K, int N) {
    __shared__ float tile[32][33];
    int nb = blockIdx.x * 32;
    int kb = blockIdx.y * 32;
    int tx = threadIdx.x;
    int ty = threadIdx.y;
#pragma unroll
    for (int i = 0; i < 4; i++) {
        int k = kb + ty + i * 8;
        tile[ty + i * 8][tx] = in[(size_t)k * N + nb + tx];
    }
    __syncthreads();
#pragma unroll
    for (int i = 0; i < 4; i++) {
        int n = nb + ty + i * 8;
        out[(size_t)n * K + kb + tx] = __float2half_rn(tile[tx][ty + i * 8]);
    }
}
// vectorized straight cast: 4 elements per thread
__global__ void castW_kernel(const float* __restrict__ in,
                             __half* __restrict__ out, int total4) {
    int idx = blockIdx.x * 256 + threadIdx.x;
    if (idx >= total4) return;
    float4 v = *(const float4*)(in + (size_t)idx * 4);
    __half2 h0, h1;
    h0.x = __float2half_rn(v.x); h0.y = __float2half_rn(v.y);
    h1.x = __float2half_rn(v.z); h1.y = __float2half_rn(v.w);
    *(__half2*)(out + (size_t)idx * 4)     = h0;
    *(__half2*)(out + (size_t)idx * 4 + 2) = h1;
}

// ---------------- build nodes (vectorized: 4 dims per thread) ----------------
__global__ void build_nodes_kernel(const float* __restrict__ g,
                                   const float* __restrict__ t,
                                   const float* __restrict__ l,
                                   float* __restrict__ nodes,
                                   __half* __restrict__ aout) {
    int idx = blockIdx.x * 256 + threadIdx.x;      // element-group of 4
    int total4 = BB * NN * (HIDD / 4);
    if (idx >= total4) return;
    int d4 = (idx % (HIDD / 4)) * 4;
    int r = (idx / (HIDD / 4)) % NN;
    int b = idx / ((HIDD / 4) * NN);
    float4 v;
    if (r == 0)            v = *(const float4*)(g + (size_t)b * HIDD + d4);
    else if (r == NN - 1)  v = *(const float4*)(l + (size_t)b * HIDD + d4);
    else                   v = *(const float4*)(t + ((size_t)b * LL + (r - 1)) * HIDD + d4);
    size_t o = ((size_t)b * NN + r) * HIDD + d4;
    *(float4*)(nodes + o) = v;
    __half2 h0, h1;
    h0.x = __float2half_rn(v.x); h0.y = __float2half_rn(v.y);
    h1.x = __float2half_rn(v.z); h1.y = __float2half_rn(v.w);
    *(__half2*)(aout + o)     = h0;
    *(__half2*)(aout + o + 2) = h1;
}

// ---------------- batched g/l fp32 SGEMM ----------------
#define BM_ 64
#define BN_ 64
#define BK_ 16
__global__ void sgemm_gl_kernel(const float* __restrict__ A0,
                                const float* __restrict__ A1,
                                const float* __restrict__ B0,
                                const float* __restrict__ B1,
                                const float* __restrict__ bias0,
                                const float* __restrict__ bias1,
                                float* __restrict__ C0,
                                float* __restrict__ C1,
                                int M, int Ncol, int K, int act,
                                int astride, int arb0, int arb1) {
    const int z = blockIdx.z;
    const float* A   = z ? A1 : A0;
    const float* Bm  = z ? B1 : B0;
    const float* bias = z ? bias1 : bias0;
    float* C = z ? C1 : C0;
    const int arb = z ? arb1 : arb0;

    __shared__ float As[BM_][BK_];
    __shared__ float Bs[BK_][BN_];
    const int tid = threadIdx.x;
    const int tm = tid >> 4;
    const int tn = tid & 15;
    const int row0 = blockIdx.y * BM_;
    const int col0 = blockIdx.x * BN_;
    float acc[4][4] = {};
    const int ar = tid >> 2;
    const int ak = (tid & 3) << 2;
    const float* Arow = nullptr;
    {
        int mm = row0 + ar;
        if (mm < M) Arow = A + (size_t)(mm * astride + arb) * K;
    }
    const int bk0 = tid >> 4;
    const int bn0 = (tid & 15) << 2;
    for (int k0 = 0; k0 < K; k0 += BK_) {
        float4 av = make_float4(0.f, 0.f, 0.f, 0.f);
        if (Arow) av = *(const float4*)(Arow + k0 + ak);
        *(float4*)(&As[ar][ak]) = av;
        float4 bv = *(const float4*)(Bm + (size_t)(k0 + bk0) * Ncol + col0 + bn0);
        *(float4*)(&Bs[bk0][bn0]) = bv;
        __syncthreads();
#pragma unroll
        for (int kk = 0; kk < BK_; kk++) {
            float a0 = As[tm * 4 + 0][kk];
            float a1 = As[tm * 4 + 1][kk];
            float a2 = As[tm * 4 + 2][kk];
            float a3 = As[tm * 4 + 3][kk];
            float4 bv2 = *(const float4*)(&Bs[kk][tn * 4]);
            acc[0][0] += a0 * bv2.x; acc[0][1] += a0 * bv2.y; acc[0][2] += a0 * bv2.z; acc[0][3] += a0 * bv2.w;
            acc[1][0] += a1 * bv2.x; acc[1][1] += a1 * bv2.y; acc[1][2] += a1 * bv2.z; acc[1][3] += a1 * bv2.w;
            acc[2][0] += a2 * bv2.x; acc[2][1] += a2 * bv2.y; acc[2][2] += a2 * bv2.z; acc[2][3] += a2 * bv2.w;
            acc[3][0] += a3 * bv2.x; acc[3][1] += a3 * bv2.y; acc[3][2] += a3 * bv2.z; acc[3][3] += a3 * bv2.w;
        }
        __syncthreads();
    }
    int n = col0 + tn * 4;
    float4 bsv = make_float4(0.f, 0.f, 0.f, 0.f);
    if (bias) bsv = *(const float4*)(bias + n);
#pragma unroll
    for (int i = 0; i < 4; i++) {
        int mm = row0 + tm * 4 + i;
        if (mm >= M) continue;
        float4 v = make_float4(acc[i][0] + bsv.x, acc[i][1] + bsv.y,
                               acc[i][2] + bsv.z, acc[i][3] + bsv.w);
        if (act == 1) {
            v.x = gelu_exact(v.x); v.y = gelu_exact(v.y);
            v.z = gelu_exact(v.z); v.w = gelu_exact(v.w);
        }
        *(float4*)(C + (size_t)mm * Ncol + n) = v;
    }
}

// ---------------- fused token attention + elu + residual + LN + fp16 out ----------------
#define QB 8
#define UMAX 20
__global__ void __launch_bounds__(512)
token_attn_ln_kernel(const __half* __restrict__ P,
                     const float* __restrict__ sq,
                     const float* __restrict__ sk,
                     const float* __restrict__ am,
                     const int* __restrict__ last,
                     float* __restrict__ nodes,
                     const float* __restrict__ gamma,
                     const float* __restrict__ beta,
                     __half* __restrict__ aout,
                     int aidx_mode) {
    int b  = blockIdx.y;
    int i0 = blockIdx.x * QB;
    int tid = threadIdx.x;

    __shared__ __align__(16) float rows[UMAX][HIDD];
    __shared__ float sks[NHEAD][UMAX];
    __shared__ float w[QB][NHEAD][13];
    __shared__ int   qk[QB][13];
    __shared__ int   qnk[QB];
    __shared__ int   ukeys[UMAX];
    __shared__ int   unk_s;
    __shared__ float wsum[16], wsq[16];
    __shared__ float lnm[QB], lnr[QB];

    if (tid == 0) {
        int lo = i0 - WINR < 0 ? 0 : i0 - WINR;
        int hi = i0 + QB - 1 + WINR;
        if (hi > LL - 1) hi = LL - 1;
        int slot_t[2 * WINR + QB];
        int un = 0;
        ukeys[un++] = 0;
        for (int t = lo; t <= hi; t++) {
            if (am[b * LL + t] > 0.f) { ukeys[un] = 1 + t; slot_t[t - lo] = un; un++; }
            else slot_t[t - lo] = -1;
        }
        int lastv = last[b];
        int locslot = -1;
        if (i0 + QB - 1 >= lastv) { locslot = un; ukeys[un++] = NN - 1; }
        unk_s = un;
        for (int q = 0; q < QB; q++) {
            int i = i0 + q;
            int nk = 0;
            qk[q][nk++] = 0;
            int l2 = i - WINR < 0 ? 0 : i - WINR;
            int h2 = i + WINR > LL - 1 ? LL - 1 : i + WINR;
            for (int t = l2; t <= h2; t++) {
                int s = slot_t[t - lo];
                if (s >= 0) qk[q][nk++] = s;
            }
            if (i >= lastv) qk[q][nk++] = locslot;
            qnk[q] = nk;
        }
    }
    __syncthreads();
    int un = unk_s;

    {
        int rsub = tid >> 7;
        int d4 = (tid & 127) * 4;
        const __half* Pb = P + (size_t)b * NN * HIDD;
        for (int r = rsub; r < un; r += 4) {
            const __half* src = Pb + (size_t)ukeys[r] * HIDD + d4;
            __half2 h01 = *(const __half2*)(src);
            __half2 h23 = *(const __half2*)(src + 2);
            float2 f01 = __half22float2(h01);
            float2 f23 = __half22float2(h23);
            rows[r][d4 + 0] = f01.x; rows[r][d4 + 1] = f01.y;
            rows[r][d4 + 2] = f23.x; rows[r][d4 + 3] = f23.y;
        }
    }
    if (tid < NHEAD * UMAX) {
        int h = tid / UMAX, kidx = tid % UMAX;
        if (kidx < un)
            sks[h][kidx] = sk[((size_t)b * NHEAD + h) * NN + ukeys[kidx]];
    }
    __syncthreads();

    if (tid < QB * NHEAD) {
        int q = tid >> 2, h = tid & 3;
        int nk = qnk[q];
        float sqv = sq[((size_t)b * NHEAD + h) * NN + 1 + i0 + q];
        float sc[13];
        float mx = -3e38f;
        for (int jj = 0; jj < nk; jj++) {
            float s = sqv + sks[h][qk[q][jj]];
            s = s >= 0.f ? s : SLOPE * s;
            sc[jj] = s;
            mx = fmaxf(mx, s);
        }
        float sum = 0.f;
        for (int jj = 0; jj < nk; jj++) {
            float e = expf(sc[jj] - mx);
            w[q][h][jj] = e;
            sum += e;
        }
        float inv = 1.f / sum;
        for (int jj = 0; jj < nk; jj++) w[q][h][jj] *= inv;
    }
    __syncthreads();

    int d = tid;
    int h = d >> 7;
    float v[QB];
#pragma unroll
    for (int q = 0; q < QB; q++) {
        int nk = qnk[q];
        float acc = 0.f;
        for (int jj = 0; jj < nk; jj++)
            acc += w[q][h][jj] * rows[qk[q][jj]][d];
        acc = acc > 0.f ? acc : expm1f(acc);
        v[q] = acc + nodes[((size_t)b * NN + 1 + i0 + q) * HIDD + d];
    }
    __syncthreads();

#pragma unroll
    for (int q = 0; q < QB; q++) rows[q][d] = v[q];
    __syncthreads();

    {
        int g = tid >> 6;
        int t = tid & 63;
        float s = 0.f, s2 = 0.f;
#pragma unroll
        for (int j = 0; j < 8; j++) {
            float x = rows[g][t + 64 * j];
            s += x; s2 += x * x;
        }
#pragma unroll
        for (int o = 16; o > 0; o >>= 1) {
            s  += __shfl_down_sync(0xffffffffu, s,  o);
            s2 += __shfl_down_sync(0xffffffffu, s2, o);
        }
        int wix = tid >> 5;
        if ((tid & 31) == 0) { wsum[wix] = s; wsq[wix] = s2; }
        __syncthreads();
        if (t == 0) {
            float ts = wsum[2 * g] + wsum[2 * g + 1];
            float tq = wsq[2 * g] + wsq[2 * g + 1];
            float mean = ts * (1.f / HIDD);
            float var = tq * (1.f / HIDD) - mean * mean;
            lnm[g] = mean;
            lnr[g] = rsqrtf(var + LNEPS);
        }
        __syncthreads();
    }

    float gmv = gamma[d], btv = beta[d];
#pragma unroll
    for (int q = 0; q < QB; q++) {
        float y = (v[q] - lnm[q]) * lnr[q] * gmv + btv;
        nodes[((size_t)b * NN + 1 + i0 + q) * HIDD + d] = y;
        size_t orow = (aidx_mode == 0) ? ((size_t)b * NN + 1 + i0 + q)
                                       : ((size_t)b * LL + i0 + q);
        aout[orow * HIDD + d] = __float2half_rn(y);
    }
}

// ---------------- dense global/local attention, J-split partials ----------------
__global__ void __launch_bounds__(512)
gl_attn_part_kernel(const __half* __restrict__ P,
                    const float* __restrict__ sq,
                    const float* __restrict__ sk,
                    const int* __restrict__ last,
                    float* __restrict__ part) {
    int b = blockIdx.y;
    int which = blockIdx.x & 1;
    int js = blockIdx.x >> 1;
    int qn = which == 0 ? 0 : NN - 1;
    int tid = threadIdx.x;
    __shared__ float ssm[NHEAD][NN];
    __shared__ float red[512];
    int lastv = last[b];
    int h = tid >> 7;
    int r = tid & 127;
    float sqv = sq[((size_t)b * NHEAD + h) * NN + qn];
    const float* skh = sk + ((size_t)b * NHEAD + h) * NN;
    float mx = -3e38f;
    for (int j = r; j < NN; j += 128) {
        bool ok = (which == 0) || (j == 0) || (j == NN - 1) ||
                  (j >= lastv + 1 && j <= LL);
        float s;
        if (ok) {
            s = sqv + skh[j];
            s = s >= 0.f ? s : SLOPE * s;
        } else s = -1e30f;
        ssm[h][j] = s;
        mx = fmaxf(mx, s);
    }
    red[tid] = mx;
    __syncthreads();
    for (int s = 64; s > 0; s >>= 1) {
        if (r < s) red[tid] = fmaxf(red[tid], red[tid + s]);
        __syncthreads();
    }
    float mhead = red[h * 128];
    __syncthreads();
    float sum = 0.f;
    for (int j = r; j < NN; j += 128) {
        float e = expf(ssm[h][j] - mhead);
        ssm[h][j] = e;
        sum += e;
    }
    red[tid] = sum;
    __syncthreads();
    for (int s = 64; s > 0; s >>= 1) {
        if (r < s) red[tid] += red[tid + s];
        __syncthreads();
    }
    float inv = 1.f / red[h * 128];
    __syncthreads();
    for (int j = r; j < NN; j += 128) ssm[h][j] *= inv;
    __syncthreads();

    const int CH = (NN + JSPLIT - 1) / JSPLIT;
    int jlo = js * CH;
    int jhi = jlo + CH; if (jhi > NN) jhi = NN;
    int d = tid;
    int hh = d >> 7;
    const __half* Pb = P + (size_t)b * NN * HIDD + d;
    float a0 = 0.f, a1 = 0.f, a2 = 0.f, a3 = 0.f;
    float a4 = 0.f, a5 = 0.f, a6 = 0.f, a7 = 0.f;
    int j = jlo;
    for (; j + 7 < jhi; j += 8) {
        a0 += ssm[hh][j + 0] * __half2float(Pb[(size_t)(j + 0) * HIDD]);
        a1 += ssm[hh][j + 1] * __half2float(Pb[(size_t)(j + 1) * HIDD]);
        a2 += ssm[hh][j + 2] * __half2float(Pb[(size_t)(j + 2) * HIDD]);
        a3 += ssm[hh][j + 3] * __half2float(Pb[(size_t)(j + 3) * HIDD]);
        a4 += ssm[hh][j + 4] * __half2float(Pb[(size_t)(j + 4) * HIDD]);
        a5 += ssm[hh][j + 5] * __half2float(Pb[(size_t)(j + 5) * HIDD]);
        a6 += ssm[hh][j + 6] * __half2float(Pb[(size_t)(j + 6) * HIDD]);
        a7 += ssm[hh][j + 7] * __half2float(Pb[(size_t)(j + 7) * HIDD]);
    }
    for (; j < jhi; j++) a0 += ssm[hh][j] * __half2float(Pb[(size_t)j * HIDD]);
    part[(((size_t)js * BB + b) * 2 + which) * HIDD + d] =
        ((a0 + a1) + (a2 + a3)) + ((a4 + a5) + (a6 + a7));
}

// ---------------- fused gl reduce + elu + residual + LN + optional fp16 out ----------------
__global__ void __launch_bounds__(512)
gl_ln_kernel(const float* __restrict__ part,
             float* __restrict__ nodes,
             const float* __restrict__ gamma,
             const float* __restrict__ beta,
             __half* __restrict__ aout,
             int write_a) {
    int row = blockIdx.x;
    int b = row >> 1;
    int which = row & 1;
    int qn = which == 0 ? 0 : NN - 1;
    int d = threadIdx.x;
    float s = 0.f;
#pragma unroll
    for (int js = 0; js < JSPLIT; js++)
        s += part[(((size_t)js * BB + b) * 2 + which) * HIDD + d];
    s = s > 0.f ? s : expm1f(s);
    size_t nrow = (size_t)b * NN + qn;
    float x = nodes[nrow * HIDD + d] + s;

    __shared__ float red[2];
    __shared__ float wsum[16], wsq[16];
    float p1 = x, p2 = x * x;
#pragma unroll
    for (int o = 16; o > 0; o >>= 1) {
        p1 += __shfl_down_sync(0xffffffffu, p1, o);
        p2 += __shfl_down_sync(0xffffffffu, p2, o);
    }
    int wix = d >> 5;
    if ((d & 31) == 0) { wsum[wix] = p1; wsq[wix] = p2; }
    __syncthreads();
    if (d == 0) {
        float ts = 0.f, tq = 0.f;
#pragma unroll
        for (int i = 0; i < 16; i++) { ts += wsum[i]; tq += wsq[i]; }
        float mean = ts * (1.f / HIDD);
        float var = tq * (1.f / HIDD) - mean * mean;
        red[0] = mean;
        red[1] = rsqrtf(var + LNEPS);
    }
    __syncthreads();
    float y = (x - red[0]) * red[1] * gamma[d] + beta[d];
    nodes[nrow * HIDD + d] = y;
    if (write_a) aout[nrow * HIDD + d] = __float2half_rn(y);
}

// ---------------- out = LN(nodes_row + y_row), single-pass (token rows) ----------------
__global__ void final_ln_kernel(const float* __restrict__ nodes,
                                int rpb, int bstride, int rbase,
                                const float* __restrict__ y,
                                const float* __restrict__ gamma,
                                const float* __restrict__ beta,
                                float* __restrict__ out) {
    int row = blockIdx.x;
    int tid = threadIdx.x;               // 256
    int pr = (row / rpb) * bstride + rbase + (row % rpb);
    size_t nb = (size_t)pr * HIDD;
    size_t yb = (size_t)row * HIDD;
    float x0 = nodes[nb + tid]       + y[yb + tid];
    float x1 = nodes[nb + tid + 256] + y[yb + tid + 256];
    __shared__ float wsum[8], wsq[8], mv[2];
    float s = x0 + x1;
    float s2 = x0 * x0 + x1 * x1;
#pragma unroll
    for (int o = 16; o > 0; o >>= 1) {
        s  += __shfl_down_sync(0xffffffffu, s,  o);
        s2 += __shfl_down_sync(0xffffffffu, s2, o);
    }
    int wix = tid >> 5;
    if ((tid & 31) == 0) { wsum[wix] = s; wsq[wix] = s2; }
    __syncthreads();
    if (tid == 0) {
        float ts = 0.f, tq = 0.f;
#pragma unroll
        for (int i = 0; i < 8; i++) { ts += wsum[i]; tq += wsq[i]; }
        float mean = ts * (1.f / HIDD);
        float var = tq * (1.f / HIDD) - mean * mean;
        mv[0] = mean;
        mv[1] = rsqrtf(var + LNEPS);
    }
    __syncthreads();
    float mean = mv[0], rstd = mv[1];
    out[yb + tid]       = (x0 - mean) * rstd * gamma[tid] + beta[tid];
    out[yb + tid + 256] = (x1 - mean) * rstd * gamma[tid + 256] + beta[tid + 256];
}

// ---------------- batched g/l final LN (32 blocks) ----------------
__global__ void gl_final_ln_kernel(const float* __restrict__ nodes,
                                   const float* __restrict__ ygl,
                                   const float* __restrict__ og,
                                   const float* __restrict__ ob,
                                   float* __restrict__ out_g,
                                   float* __restrict__ out_l) {
    int idx = blockIdx.x;
    int which = idx >> 4;
    int b = idx & 15;
    int tid = threadIdx.x;
    int qn = which == 0 ? 0 : NN - 1;
    const float* gamma = og + (which == 0 ? 0 : 2 * HIDD);
    const float* beta  = ob + (which == 0 ? 0 : 2 * HIDD);
    float* out = (which == 0 ? out_g : out_l) + (size_t)b * HIDD;
    size_t nb = ((size_t)b * NN + qn) * HIDD;
    size_t yb = ((size_t)which * BB + b) * HIDD;
    float x0 = nodes[nb + tid]       + ygl[yb + tid];
    float x1 = nodes[nb + tid + 256] + ygl[yb + tid + 256];
    __shared__ float wsum[8], wsq[8], mv[2];
    float s = x0 + x1;
    float s2 = x0 * x0 + x1 * x1;
#pragma unroll
    for (int o = 16; o > 0; o >>= 1) {
        s  += __shfl_down_sync(0xffffffffu, s,  o);
        s2 += __shfl_down_sync(0xffffffffu, s2, o);
    }
    int wix = tid >> 5;
    if ((tid & 31) == 0) { wsum[wix] = s; wsq[wix] = s2; }
    __syncthreads();
    if (tid == 0) {
        float ts = 0.f, tq = 0.f;
#pragma unroll
        for (int i = 0; i < 8; i++) { ts += wsum[i]; tq += wsq[i]; }
        float mean = ts * (1.f / HIDD);
        float var = tq * (1.f / HIDD) - mean * mean;
        mv[0] = mean;
        mv[1] = rsqrtf(var + LNEPS);
    }
    __syncthreads();
    float mean = mv[0], rstd = mv[1];
    out[tid]       = (x0 - mean) * rstd * gamma[tid] + beta[tid];
    out[tid + 256] = (x1 - mean) * rstd * gamma[tid + 256] + beta[tid + 256];
}

// ---------------- orchestration ----------------
extern "C" void kernel_launch(void* const* d_in, const int* in_sizes, int n_in,
                              void* d_out, int out_size) {
    const float* ge   = (const float*)d_in[0];
    const float* te   = (const float*)d_in[1];
    const float* le   = (const float*)d_in[2];
    const float* am   = (const float*)d_in[3];
    const int*   last = (const int*)  d_in[4];
    const float* W    = (const float*)d_in[5];
    const float* ga   = (const float*)d_in[6];
    const float* lng  = (const float*)d_in[7];
    const float* lnb  = (const float*)d_in[8];
    const float* w1   = (const float*)d_in[9];
    const float* b1   = (const float*)d_in[10];
    const float* w2   = (const float*)d_in[11];
    const float* b2   = (const float*)d_in[12];
    const float* og   = (const float*)d_in[13];
    const float* ob   = (const float*)d_in[14];
    float* out = (float*)d_out;

    float *nodes, *sqp, *skp, *ffn, *midgl, *ygl, *glpart;
    __half *proj, *Aproj, *Atok, *Amid, *Bw, *B1, *B2;
    cudaGetSymbolAddress((void**)&nodes, d_nodes);
    cudaGetSymbolAddress((void**)&sqp,   d_sq);
    cudaGetSymbolAddress((void**)&skp,   d_sk);
    cudaGetSymbolAddress((void**)&ffn,   d_ffn);
    cudaGetSymbolAddress((void**)&midgl, d_midgl);
    cudaGetSymbolAddress((void**)&ygl,   d_ygl);
    cudaGetSymbolAddress((void**)&glpart,d_glpart);
    cudaGetSymbolAddress((void**)&proj,  d_proj);
    cudaGetSymbolAddress((void**)&Aproj, d_Aproj);
    cudaGetSymbolAddress((void**)&Atok,  d_Atok);
    cudaGetSymbolAddress((void**)&Amid,  d_Amid);
    cudaGetSymbolAddress((void**)&Bw,    d_Bw);
    cudaGetSymbolAddress((void**)&B1,    d_B1);
    cudaGetSymbolAddress((void**)&B2,    d_B2);

    cudaFuncSetAttribute(mma_gemm_kernel,
                         cudaFuncAttributeMaxDynamicSharedMemorySize, GM_SMEM);

    const int MN = BB * NN;   // 16416
    const int MT = BB * LL;   // 16384

    build_nodes_kernel<<<(BB * NN * (HIDD / 4) + 255) / 256, 256>>>(ge, te, le, nodes, Aproj);

    castW_kernel<<<(NLAY * HIDD * HIDD / 4 + 255) / 256, 256>>>(W, Bw, NLAY * HIDD * HIDD / 4);
    splitT1_kernel<<<dim3(FF / 32, HIDD / 32), dim3(32, 8)>>>(w1 + (size_t)1 * HIDD * FF, B1, HIDD, FF);
    splitT1_kernel<<<dim3(HIDD / 32, FF / 32), dim3(32, 8)>>>(w2 + (size_t)1 * FF * HIDD, B2, FF, HIDD);

    for (int k = 0; k < NLAY; k++) {
        mma_gemm_kernel<<<dim3(NHEAD, (MN + 127) / 128), 256, GM_SMEM>>>(
            Aproj, Bw + (size_t)k * HIDD * HIDD, nullptr, nullptr, proj,
            MN, 8, HIDD, 0, 3, HIDD,
            ga + (size_t)k * NHEAD * 2 * DH, sqp, skp);
        gl_attn_part_kernel<<<dim3(2 * JSPLIT, BB), 512>>>(proj, sqp, skp, last, glpart);
        if (k == 0) {
            token_attn_ln_kernel<<<dim3(LL / QB, BB), 512>>>(
                proj, sqp, skp, am, last, nodes, lng, lnb, Aproj, 0);
            gl_ln_kernel<<<BB * 2, 512>>>(glpart, nodes, lng, lnb, Aproj, 1);
        } else {
            token_attn_ln_kernel<<<dim3(LL / QB, BB), 512>>>(
                proj, sqp, skp, am, last, nodes, lng + k * HIDD, lnb + k * HIDD, Atok, 1);
            gl_ln_kernel<<<BB * 2, 512>>>(glpart, nodes, lng + k * HIDD, lnb + k * HIDD,
                                          nullptr, 0);
        }
    }

    // token FFN
    mma_gemm_kernel<<<dim3(FF / 128, MT / 128), 256, GM_SMEM>>>(
        Atok, B1, b1 + 1 * FF, nullptr, Amid, MT, 8, HIDD, 0, 2, FF,
        nullptr, nullptr, nullptr);
    mma_gemm_kernel<<<dim3(HIDD / 128, MT / 128), 256, GM_SMEM>>>(
        Amid, B2, b2 + 1 * HIDD, ffn, nullptr, MT, 32, FF, HIDD, 1, 0,
        nullptr, nullptr, nullptr);
    final_ln_kernel<<<MT, 256>>>(nodes, LL, NN, 1, ffn,
                                 og + 1 * HIDD, ob + 1 * HIDD, out + BB * HIDD);

    // g/l FFN, batched over z
    sgemm_gl_kernel<<<dim3(FF / BN_, 1, 2), 256>>>(
        nodes, nodes,
        w1 + (size_t)0, w1 + (size_t)2 * HIDD * FF,
        b1 + 0, b1 + 2 * FF,
        midgl, midgl + (size_t)BB * FF,
        BB, FF, HIDD, /*gelu*/1, NN, 0, NN - 1);
    sgemm_gl_kernel<<<dim3(HIDD / BN_, 1, 2), 256>>>(
        midgl, midgl + (size_t)BB * FF,
        w2 + (size_t)0, w2 + (size_t)2 * FF * HIDD,
        b2 + 0, b2 + 2 * HIDD,
        ygl, ygl + (size_t)BB * HIDD,
        BB, HIDD, FF, 0, 1, 0, 0);
    gl_final_ln_kernel<<<2 * BB, 256>>>(nodes, ygl, og, ob,
                                        out,
                                        out + BB * HIDD + (size_t)BB * LL * HIDD);
}

// round 16
// speedup vs baseline: 1.1021x; 1.0729x over previous
#include <cuda_runtime.h>
#include <cuda_fp16.h>
#include <math.h>
#include <stdint.h>

// ---------------- problem constants ----------------
#define BB    16
#define LL    1024
#define NN    1026          // L + 2
#define HIDD  512
#define NHEAD 4
#define DH    128
#define NLAY  2
#define WINR  5
#define FF    2048          // 4*HID
#define SLOPE 0.2f
#define LNEPS 1e-5f
#define JSPLIT 4

// ---------------- scratch (device globals; no allocation allowed) ----------------
__device__ float d_nodes[(size_t)BB * NN * HIDD];
__device__ float d_sq   [(size_t)BB * NHEAD * NN];
__device__ float d_sk   [(size_t)BB * NHEAD * NN];
__device__ float d_ffn  [(size_t)BB * LL * HIDD];
__device__ float d_midgl[(size_t)2 * BB * FF];     // [g | l]
__device__ float d_ygl  [(size_t)2 * BB * HIDD];   // [g | l]
__device__ float d_glpart[(size_t)JSPLIT * BB * 2 * HIDD];

// fp16 buffers
__device__ __half d_proj [(size_t)(BB * NN) * HIDD];
__device__ __half d_Aproj[(size_t)(BB * NN) * HIDD];
__device__ __half d_Atok [(size_t)(BB * LL) * HIDD];
__device__ __half d_Amid [(size_t)(BB * LL) * FF];
__device__ __half d_Bw   [(size_t)NLAY * HIDD * HIDD];
__device__ __half d_B1   [(size_t)FF   * HIDD];
__device__ __half d_B2   [(size_t)HIDD * FF];

// ---------------- helpers ----------------
__device__ __forceinline__ float gelu_exact(float x) {
    return 0.5f * x * (1.0f + erff(x * 0.70710678118654752f));
}
__device__ __forceinline__ uint32_t smem_u32(const void* p) {
    uint32_t a;
    asm("{ .reg .u64 t; cvta.to.shared.u64 t, %1; cvt.u32.u64 %0, t; }" : "=r"(a) : "l"(p));
    return a;
}
__device__ __forceinline__ void cpa16(uint32_t dst, const void* src, bool pred) {
    int sz = pred ? 16 : 0;
    asm volatile("cp.async.cg.shared.global [%0], [%1], 16, %2;" :: "r"(dst), "l"(src), "r"(sz));
}
__device__ __forceinline__ void ldm_x4(uint32_t* r, uint32_t addr) {
    asm volatile("ldmatrix.sync.aligned.m8n8.x4.shared.b16 {%0, %1, %2, %3}, [%4];"
                 : "=r"(r[0]), "=r"(r[1]), "=r"(r[2]), "=r"(r[3]) : "r"(addr));
}
__device__ __forceinline__ void mma16816(float* d, const uint32_t* a, const uint32_t* b) {
    asm volatile("mma.sync.aligned.m16n8k16.row.col.f32.f16.f16.f32 "
                 "{%0, %1, %2, %3}, {%4, %5, %6, %7}, {%8, %9}, {%0, %1, %2, %3};"
                 : "+f"(d[0]), "+f"(d[1]), "+f"(d[2]), "+f"(d[3])
                 : "r"(a[0]), "r"(a[1]), "r"(a[2]), "r"(a[3]), "r"(b[0]), "r"(b[1]));
}
__device__ __forceinline__ uint32_t sw128(uint32_t off) {
    return off ^ ((off >> 3) & 0x70);
}

// ---------------- HMMA fp16 GEMM, 3-stage pipeline ----------------
// mode 0: Cf = acc ; mode 1: Cf = acc + bias ;
// mode 2: Cb[m*K0+n] = fp16(gelu(acc+bias))
// mode 3: Cb[m*K0+n] = fp16(acc) AND fused sq/sk emit (grid.x==NHEAD)
#define GM_SMEM (98304)
__global__ void __launch_bounds__(256, 2)
mma_gemm_kernel(const __half* __restrict__ A,
                const __half* __restrict__ B,
                const float* __restrict__ bias,
                float* __restrict__ Cf,
                __half* __restrict__ Cb,
                int M, int Kt, int ldk, int ldc, int mode, int K0,
                const float* __restrict__ gq,
                float* __restrict__ sqo,
                float* __restrict__ sko) {
    extern __shared__ __align__(1024) char dynsm[];
    const uint32_t sbase = smem_u32(dynsm);
    const int tid  = threadIdx.x;
    const int lane = tid & 31;
    const int wid  = tid >> 5;
    const int wm   = wid & 1;
    const int wn   = wid >> 1;
    const int m0 = blockIdx.y * 128;
    const int n0 = blockIdx.x * 128;

    const char* Ag = (const char*)A;
    const char* Bg = (const char*)B;
    const size_t ldkb = (size_t)ldk * 2;

    float acc[4][4][4];
#pragma unroll
    for (int i = 0; i < 4; i++)
#pragma unroll
        for (int j = 0; j < 4; j++)
#pragma unroll
            for (int c = 0; c < 4; c++) acc[i][j][c] = 0.f;

    const int lrow[4] = { (0 * 256 + tid) >> 3, (1 * 256 + tid) >> 3,
                          (2 * 256 + tid) >> 3, (3 * 256 + tid) >> 3 };
    const int lch = tid & 7;

    auto load_tile = [&](int buf, int t) {
        size_t kb = (size_t)t * 128 + lch * 16;
        uint32_t sA = sbase + buf * 16384u;
        uint32_t sB = sbase + 49152u + buf * 16384u;
#pragma unroll
        for (int i = 0; i < 4; i++) {
            int row = lrow[i];
            uint32_t off = (uint32_t)(row * 128 + lch * 16);
            int m = m0 + row;
            cpa16(sA + sw128(off), Ag + (size_t)(m < M ? m : 0) * ldkb + kb, m < M);
        }
#pragma unroll
        for (int i = 0; i < 4; i++) {
            int row = lrow[i];
            uint32_t off = (uint32_t)(row * 128 + lch * 16);
            cpa16(sB + sw128(off), Bg + (size_t)(n0 + row) * ldkb + kb, true);
        }
        asm volatile("cp.async.commit_group;" ::: "memory");
    };

    auto compute_tile = [&](int buf) {
        uint32_t sA = sbase + buf * 16384u;
        uint32_t sB = sbase + 49152u + buf * 16384u;
        const int r15 = lane & 15;
        const int kh16 = (lane & 16);
#pragma unroll
        for (int ks = 0; ks < 4; ks++) {
            uint32_t kb = ks * 32 + kh16;
            uint32_t a[4][4];
#pragma unroll
            for (int tm = 0; tm < 4; tm++) {
                uint32_t off = (uint32_t)((wm * 64 + tm * 16 + r15) * 128) + kb;
                ldm_x4(a[tm], sA + sw128(off));
            }
            uint32_t b[4][2];
#pragma unroll
            for (int p = 0; p < 2; p++) {
                uint32_t r[4];
                uint32_t off = (uint32_t)((wn * 32 + p * 16 + r15) * 128) + kb;
                ldm_x4(r, sB + sw128(off));
                b[2 * p + 0][0] = r[0]; b[2 * p + 1][0] = r[1];
                b[2 * p + 0][1] = r[2]; b[2 * p + 1][1] = r[3];
            }
#pragma unroll
            for (int tm = 0; tm < 4; tm++)
#pragma unroll
                for (int tn = 0; tn < 4; tn++)
                    mma16816(acc[tm][tn], a[tm], b[tn]);
        }
    };

    load_tile(0, 0);
    load_tile(1, 1);
    int buf = 0;
    for (int t = 0; t < Kt; t++) {
        asm volatile("cp.async.wait_group 1;" ::: "memory");
        __syncthreads();
        if (t + 2 < Kt) {
            int nb = buf + 2; if (nb >= 3) nb -= 3;
            load_tile(nb, t + 2);
        } else {
            asm volatile("cp.async.commit_group;" ::: "memory");
        }
        compute_tile(buf);
        if (++buf == 3) buf = 0;
    }

    const int rbase = lane >> 2;
    const int cbase = 2 * (lane & 3);

    float a1v[4][2], a2v[4][2];
    if (mode == 3) {
        const float* ah = gq + blockIdx.x * (2 * DH);
#pragma unroll
        for (int tn = 0; tn < 4; tn++) {
            int c0 = wn * 32 + tn * 8 + cbase;
            a1v[tn][0] = ah[c0];       a1v[tn][1] = ah[c0 + 1];
            a2v[tn][0] = ah[DH + c0];  a2v[tn][1] = ah[DH + c0 + 1];
        }
    }
    float p1[4][2], p2[4][2];
#pragma unroll
    for (int tm = 0; tm < 4; tm++) { p1[tm][0] = p1[tm][1] = p2[tm][0] = p2[tm][1] = 0.f; }

#pragma unroll
    for (int tm = 0; tm < 4; tm++) {
#pragma unroll
        for (int half = 0; half < 2; half++) {
            int m = m0 + wm * 64 + tm * 16 + rbase + half * 8;
            if (m >= M) continue;
#pragma unroll
            for (int tn = 0; tn < 4; tn++) {
                int n = n0 + wn * 32 + tn * 8 + cbase;
                float v0 = acc[tm][tn][half * 2 + 0];
                float v1 = acc[tm][tn][half * 2 + 1];
                if (mode == 2) {
                    __half2 hv;
                    hv.x = __float2half_rn(gelu_exact(v0 + bias[n]));
                    hv.y = __float2half_rn(gelu_exact(v1 + bias[n + 1]));
                    *(__half2*)(Cb + (size_t)m * K0 + n) = hv;
                } else if (mode == 3) {
                    __half2 hv;
                    hv.x = __float2half_rn(v0);
                    hv.y = __float2half_rn(v1);
                    *(__half2*)(Cb + (size_t)m * K0 + n) = hv;
                    p1[tm][half] += v0 * a1v[tn][0] + v1 * a1v[tn][1];
                    p2[tm][half] += v0 * a2v[tn][0] + v1 * a2v[tn][1];
                } else {
                    if (mode == 1) { v0 += bias[n]; v1 += bias[n + 1]; }
                    float2 o; o.x = v0; o.y = v1;
                    *(float2*)(Cf + (size_t)m * ldc + n) = o;
                }
            }
        }
    }

    if (mode == 3) {
        __syncthreads();
        float* red1 = (float*)dynsm;
        float* red2 = red1 + 128 * 16;
        int slot = wn * 4 + (lane & 3);
#pragma unroll
        for (int tm = 0; tm < 4; tm++)
#pragma unroll
            for (int half = 0; half < 2; half++) {
                int rb = wm * 64 + tm * 16 + rbase + half * 8;
                red1[rb * 16 + slot] = p1[tm][half];
                red2[rb * 16 + slot] = p2[tm][half];
            }
        __syncthreads();
        if (tid < 128) {
            int m = m0 + tid;
            if (m < M) {
                float s1 = 0.f, s2 = 0.f;
#pragma unroll
                for (int i = 0; i < 16; i++) {
                    s1 += red1[tid * 16 + i];
                    s2 += red2[tid * 16 + i];
                }
                int b = m / NN, n = m % NN;
                size_t o = ((size_t)b * NHEAD + blockIdx.x) * NN + n;
                sqo[o] = s1;
                sko[o] = s2;
            }
        }
    }
}

// ---------------- weight conversion ----------------
__global__ void splitT1_kernel(const float* __restrict__ in,
                               __half* __restrict__ out,
                               int K, int N) {
    __shared__ float tile[32][33];
    int nb = blockIdx.x * 32;
    int kb = blockIdx.y * 32;
    int tx = threadIdx.x;
    int ty = threadIdx.y;
#pragma unroll
    for (int i = 0; i < 4; i++) {
        int k = kb + ty + i * 8;
        tile[ty + i * 8][tx] = in[(size_t)k * N + nb + tx];
    }
    __syncthreads();
#pragma unroll
    for (int i = 0; i < 4; i++) {
        int n = nb + ty + i * 8;
        out[(size_t)n * K + kb + tx] = __float2half_rn(tile[tx][ty + i * 8]);
    }
}
__global__ void castW_kernel(const float* __restrict__ in,
                             __half* __restrict__ out, int total4) {
    int idx = blockIdx.x * 256 + threadIdx.x;
    if (idx >= total4) return;
    float4 v = *(const float4*)(in + (size_t)idx * 4);
    __half2 h0, h1;
    h0.x = __float2half_rn(v.x); h0.y = __float2half_rn(v.y);
    h1.x = __float2half_rn(v.z); h1.y = __float2half_rn(v.w);
    *(__half2*)(out + (size_t)idx * 4)     = h0;
    *(__half2*)(out + (size_t)idx * 4 + 2) = h1;
}

// ---------------- build nodes (vectorized) ----------------
__global__ void build_nodes_kernel(const float* __restrict__ g,
                                   const float* __restrict__ t,
                                   const float* __restrict__ l,
                                   float* __restrict__ nodes,
                                   __half* __restrict__ aout) {
    int idx = blockIdx.x * 256 + threadIdx.x;
    int total4 = BB * NN * (HIDD / 4);
    if (idx >= total4) return;
    int d4 = (idx % (HIDD / 4)) * 4;
    int r = (idx / (HIDD / 4)) % NN;
    int b = idx / ((HIDD / 4) * NN);
    float4 v;
    if (r == 0)            v = *(const float4*)(g + (size_t)b * HIDD + d4);
    else if (r == NN - 1)  v = *(const float4*)(l + (size_t)b * HIDD + d4);
    else                   v = *(const float4*)(t + ((size_t)b * LL + (r - 1)) * HIDD + d4);
    size_t o = ((size_t)b * NN + r) * HIDD + d4;
    *(float4*)(nodes + o) = v;
    __half2 h0, h1;
    h0.x = __float2half_rn(v.x); h0.y = __float2half_rn(v.y);
    h1.x = __float2half_rn(v.z); h1.y = __float2half_rn(v.w);
    *(__half2*)(aout + o)     = h0;
    *(__half2*)(aout + o + 2) = h1;
}

// ---------------- batched g/l fp32 SGEMM ----------------
#define BM_ 64
#define BN_ 64
#define BK_ 16
__global__ void sgemm_gl_kernel(const float* __restrict__ A0,
                                const float* __restrict__ A1,
                                const float* __restrict__ B0,
                                const float* __restrict__ B1,
                                const float* __restrict__ bias0,
                                const float* __restrict__ bias1,
                                float* __restrict__ C0,
                                float* __restrict__ C1,
                                int M, int Ncol, int K, int act,
                                int astride, int arb0, int arb1) {
    const int z = blockIdx.z;
    const float* A   = z ? A1 : A0;
    const float* Bm  = z ? B1 : B0;
    const float* bias = z ? bias1 : bias0;
    float* C = z ? C1 : C0;
    const int arb = z ? arb1 : arb0;

    __shared__ float As[BM_][BK_];
    __shared__ float Bs[BK_][BN_];
    const int tid = threadIdx.x;
    const int tm = tid >> 4;
    const int tn = tid & 15;
    const int row0 = blockIdx.y * BM_;
    const int col0 = blockIdx.x * BN_;
    float acc[4][4] = {};
    const int ar = tid >> 2;
    const int ak = (tid & 3) << 2;
    const float* Arow = nullptr;
    {
        int mm = row0 + ar;
        if (mm < M) Arow = A + (size_t)(mm * astride + arb) * K;
    }
    const int bk0 = tid >> 4;
    const int bn0 = (tid & 15) << 2;
    for (int k0 = 0; k0 < K; k0 += BK_) {
        float4 av = make_float4(0.f, 0.f, 0.f, 0.f);
        if (Arow) av = *(const float4*)(Arow + k0 + ak);
        *(float4*)(&As[ar][ak]) = av;
        float4 bv = *(const float4*)(Bm + (size_t)(k0 + bk0) * Ncol + col0 + bn0);
        *(float4*)(&Bs[bk0][bn0]) = bv;
        __syncthreads();
#pragma unroll
        for (int kk = 0; kk < BK_; kk++) {
            float a0 = As[tm * 4 + 0][kk];
            float a1 = As[tm * 4 + 1][kk];
            float a2 = As[tm * 4 + 2][kk];
            float a3 = As[tm * 4 + 3][kk];
            float4 bv2 = *(const float4*)(&Bs[kk][tn * 4]);
            acc[0][0] += a0 * bv2.x; acc[0][1] += a0 * bv2.y; acc[0][2] += a0 * bv2.z; acc[0][3] += a0 * bv2.w;
            acc[1][0] += a1 * bv2.x; acc[1][1] += a1 * bv2.y; acc[1][2] += a1 * bv2.z; acc[1][3] += a1 * bv2.w;
            acc[2][0] += a2 * bv2.x; acc[2][1] += a2 * bv2.y; acc[2][2] += a2 * bv2.z; acc[2][3] += a2 * bv2.w;
            acc[3][0] += a3 * bv2.x; acc[3][1] += a3 * bv2.y; acc[3][2] += a3 * bv2.z; acc[3][3] += a3 * bv2.w;
        }
        __syncthreads();
    }
    int n = col0 + tn * 4;
    float4 bsv = make_float4(0.f, 0.f, 0.f, 0.f);
    if (bias) bsv = *(const float4*)(bias + n);
#pragma unroll
    for (int i = 0; i < 4; i++) {
        int mm = row0 + tm * 4 + i;
        if (mm >= M) continue;
        float4 v = make_float4(acc[i][0] + bsv.x, acc[i][1] + bsv.y,
                               acc[i][2] + bsv.z, acc[i][3] + bsv.w);
        if (act == 1) {
            v.x = gelu_exact(v.x); v.y = gelu_exact(v.y);
            v.z = gelu_exact(v.z); v.w = gelu_exact(v.w);
        }
        *(float4*)(C + (size_t)mm * Ncol + n) = v;
    }
}

// ---------------- fused token attention + elu + residual + LN + fp16 out ----------------
#define QB 8
#define UMAX 20
__global__ void __launch_bounds__(512)
token_attn_ln_kernel(const __half* __restrict__ P,
                     const float* __restrict__ sq,
                     const float* __restrict__ sk,
                     const float* __restrict__ am,
                     const int* __restrict__ last,
                     float* __restrict__ nodes,
                     const float* __restrict__ gamma,
                     const float* __restrict__ beta,
                     __half* __restrict__ aout,
                     int aidx_mode) {
    int b  = blockIdx.y;
    int i0 = blockIdx.x * QB;
    int tid = threadIdx.x;

    __shared__ __align__(16) float rows[UMAX][HIDD];
    __shared__ float sks[NHEAD][UMAX];
    __shared__ float w[QB][NHEAD][13];
    __shared__ int   qk[QB][13];
    __shared__ int   qnk[QB];
    __shared__ int   ukeys[UMAX];
    __shared__ int   unk_s;
    __shared__ float wsum[16], wsq[16];
    __shared__ float lnm[QB], lnr[QB];

    if (tid == 0) {
        int lo = i0 - WINR < 0 ? 0 : i0 - WINR;
        int hi = i0 + QB - 1 + WINR;
        if (hi > LL - 1) hi = LL - 1;
        int slot_t[2 * WINR + QB];
        int un = 0;
        ukeys[un++] = 0;
        for (int t = lo; t <= hi; t++) {
            if (am[b * LL + t] > 0.f) { ukeys[un] = 1 + t; slot_t[t - lo] = un; un++; }
            else slot_t[t - lo] = -1;
        }
        int lastv = last[b];
        int locslot = -1;
        if (i0 + QB - 1 >= lastv) { locslot = un; ukeys[un++] = NN - 1; }
        unk_s = un;
        for (int q = 0; q < QB; q++) {
            int i = i0 + q;
            int nk = 0;
            qk[q][nk++] = 0;
            int l2 = i - WINR < 0 ? 0 : i - WINR;
            int h2 = i + WINR > LL - 1 ? LL - 1 : i + WINR;
            for (int t = l2; t <= h2; t++) {
                int s = slot_t[t - lo];
                if (s >= 0) qk[q][nk++] = s;
            }
            if (i >= lastv) qk[q][nk++] = locslot;
            qnk[q] = nk;
        }
    }
    __syncthreads();
    int un = unk_s;

    {
        int rsub = tid >> 7;
        int d4 = (tid & 127) * 4;
        const __half* Pb = P + (size_t)b * NN * HIDD;
        for (int r = rsub; r < un; r += 4) {
            uint2 raw = *(const uint2*)(Pb + (size_t)ukeys[r] * HIDD + d4);
            __half2 h01 = *(__half2*)&raw.x;
            __half2 h23 = *(__half2*)&raw.y;
            float2 f01 = __half22float2(h01);
            float2 f23 = __half22float2(h23);
            rows[r][d4 + 0] = f01.x; rows[r][d4 + 1] = f01.y;
            rows[r][d4 + 2] = f23.x; rows[r][d4 + 3] = f23.y;
        }
    }
    if (tid < NHEAD * UMAX) {
        int h = tid / UMAX, kidx = tid % UMAX;
        if (kidx < un)
            sks[h][kidx] = sk[((size_t)b * NHEAD + h) * NN + ukeys[kidx]];
    }
    __syncthreads();

    if (tid < QB * NHEAD) {
        int q = tid >> 2, h = tid & 3;
        int nk = qnk[q];
        float sqv = sq[((size_t)b * NHEAD + h) * NN + 1 + i0 + q];
        float sc[13];
        float mx = -3e38f;
        for (int jj = 0; jj < nk; jj++) {
            float s = sqv + sks[h][qk[q][jj]];
            s = s >= 0.f ? s : SLOPE * s;
            sc[jj] = s;
            mx = fmaxf(mx, s);
        }
        float sum = 0.f;
        for (int jj = 0; jj < nk; jj++) {
            float e = expf(sc[jj] - mx);
            w[q][h][jj] = e;
            sum += e;
        }
        float inv = 1.f / sum;
        for (int jj = 0; jj < nk; jj++) w[q][h][jj] *= inv;
    }
    __syncthreads();

    int d = tid;
    int h = d >> 7;
    float v[QB];
#pragma unroll
    for (int q = 0; q < QB; q++) {
        int nk = qnk[q];
        float acc = 0.f;
        for (int jj = 0; jj < nk; jj++)
            acc += w[q][h][jj] * rows[qk[q][jj]][d];
        acc = acc > 0.f ? acc : expm1f(acc);
        v[q] = acc + nodes[((size_t)b * NN + 1 + i0 + q) * HIDD + d];
    }
    __syncthreads();

#pragma unroll
    for (int q = 0; q < QB; q++) rows[q][d] = v[q];
    __syncthreads();

    {
        int g = tid >> 6;
        int t = tid & 63;
        float s = 0.f, s2 = 0.f;
#pragma unroll
        for (int j = 0; j < 8; j++) {
            float x = rows[g][t + 64 * j];
            s += x; s2 += x * x;
        }
#pragma unroll
        for (int o = 16; o > 0; o >>= 1) {
            s  += __shfl_down_sync(0xffffffffu, s,  o);
            s2 += __shfl_down_sync(0xffffffffu, s2, o);
        }
        int wix = tid >> 5;
        if ((tid & 31) == 0) { wsum[wix] = s; wsq[wix] = s2; }
        __syncthreads();
        if (t == 0) {
            float ts = wsum[2 * g] + wsum[2 * g + 1];
            float tq = wsq[2 * g] + wsq[2 * g + 1];
            float mean = ts * (1.f / HIDD);
            float var = tq * (1.f / HIDD) - mean * mean;
            lnm[g] = mean;
            lnr[g] = rsqrtf(var + LNEPS);
        }
        __syncthreads();
    }

    float gmv = gamma[d], btv = beta[d];
#pragma unroll
    for (int q = 0; q < QB; q++) {
        float y = (v[q] - lnm[q]) * lnr[q] * gmv + btv;
        nodes[((size_t)b * NN + 1 + i0 + q) * HIDD + d] = y;
        size_t orow = (aidx_mode == 0) ? ((size_t)b * NN + 1 + i0 + q)
                                       : ((size_t)b * LL + i0 + q);
        aout[orow * HIDD + d] = __float2half_rn(y);
    }
}

// ---------------- dense global/local attention, J-split partials ----------------
// PV phase restructured: 256 threads own d-pairs (half2 loads), 2-way j split.
__global__ void __launch_bounds__(512)
gl_attn_part_kernel(const __half* __restrict__ P,
                    const float* __restrict__ sq,
                    const float* __restrict__ sk,
                    const int* __restrict__ last,
                    float* __restrict__ part) {
    int b = blockIdx.y;
    int which = blockIdx.x & 1;
    int js = blockIdx.x >> 1;
    int qn = which == 0 ? 0 : NN - 1;
    int tid = threadIdx.x;
    __shared__ float ssm[NHEAD][NN];
    __shared__ float red[512];
    __shared__ float2 pvbuf[2][256];
    int lastv = last[b];
    int h = tid >> 7;
    int r = tid & 127;
    float sqv = sq[((size_t)b * NHEAD + h) * NN + qn];
    const float* skh = sk + ((size_t)b * NHEAD + h) * NN;
    float mx = -3e38f;
    for (int j = r; j < NN; j += 128) {
        bool ok = (which == 0) || (j == 0) || (j == NN - 1) ||
                  (j >= lastv + 1 && j <= LL);
        float s;
        if (ok) {
            s = sqv + skh[j];
            s = s >= 0.f ? s : SLOPE * s;
        } else s = -1e30f;
        ssm[h][j] = s;
        mx = fmaxf(mx, s);
    }
    red[tid] = mx;
    __syncthreads();
    for (int s = 64; s > 0; s >>= 1) {
        if (r < s) red[tid] = fmaxf(red[tid], red[tid + s]);
        __syncthreads();
    }
    float mhead = red[h * 128];
    __syncthreads();
    float sum = 0.f;
    for (int j = r; j < NN; j += 128) {
        float e = expf(ssm[h][j] - mhead);
        ssm[h][j] = e;
        sum += e;
    }
    red[tid] = sum;
    __syncthreads();
    for (int s = 64; s > 0; s >>= 1) {
        if (r < s) red[tid] += red[tid + s];
        __syncthreads();
    }
    float inv = 1.f / red[h * 128];
    __syncthreads();
    for (int j = r; j < NN; j += 128) ssm[h][j] *= inv;
    __syncthreads();

    const int CH = (NN + JSPLIT - 1) / JSPLIT;
    int jlo = js * CH;
    int jhi = jlo + CH; if (jhi > NN) jhi = NN;

    int dp = tid & 255;          // d-pair index, d = 2*dp
    int jh = tid >> 8;           // 0/1 j-parity split
    int hh = dp >> 6;            // head of d = 2*dp
    const __half2* Pb2 = (const __half2*)(P + (size_t)b * NN * HIDD) + dp;
    float2 accA = make_float2(0.f, 0.f);
    float2 accB = make_float2(0.f, 0.f);
    int j = jlo + jh;
    for (; j + 6 < jhi; j += 8) {
        float2 q0 = __half22float2(Pb2[(size_t)(j + 0) * 256]);
        float2 q1 = __half22float2(Pb2[(size_t)(j + 2) * 256]);
        float2 q2 = __half22float2(Pb2[(size_t)(j + 4) * 256]);
        float2 q3 = __half22float2(Pb2[(size_t)(j + 6) * 256]);
        float w0 = ssm[hh][j + 0], w1 = ssm[hh][j + 2];
        float w2 = ssm[hh][j + 4], w3 = ssm[hh][j + 6];
        accA.x += w0 * q0.x + w1 * q1.x;
        accA.y += w0 * q0.y + w1 * q1.y;
        accB.x += w2 * q2.x + w3 * q3.x;
        accB.y += w2 * q2.y + w3 * q3.y;
    }
    for (; j < jhi; j += 2) {
        float2 q = __half22float2(Pb2[(size_t)j * 256]);
        float wv = ssm[hh][j];
        accA.x += wv * q.x;
        accA.y += wv * q.y;
    }
    pvbuf[jh][dp] = make_float2(accA.x + accB.x, accA.y + accB.y);
    __syncthreads();
    if (tid < 256) {
        float2 a = pvbuf[0][tid];
        float2 c = pvbuf[1][tid];
        float2 o = make_float2(a.x + c.x, a.y + c.y);
        *(float2*)(&part[(((size_t)js * BB + b) * 2 + which) * HIDD + 2 * tid]) = o;
    }
}

// ---------------- fused gl reduce + elu + residual + LN + optional fp16 out ----------------
__global__ void __launch_bounds__(512)
gl_ln_kernel(const float* __restrict__ part,
             float* __restrict__ nodes,
             const float* __restrict__ gamma,
             const float* __restrict__ beta,
             __half* __restrict__ aout,
             int write_a) {
    int row = blockIdx.x;
    int b = row >> 1;
    int which = row & 1;
    int qn = which == 0 ? 0 : NN - 1;
    int d = threadIdx.x;
    float s = 0.f;
#pragma unroll
    for (int js = 0; js < JSPLIT; js++)
        s += part[(((size_t)js * BB + b) * 2 + which) * HIDD + d];
    s = s > 0.f ? s : expm1f(s);
    size_t nrow = (size_t)b * NN + qn;
    float x = nodes[nrow * HIDD + d] + s;

    __shared__ float red[2];
    __shared__ float wsum[16], wsq[16];
    float p1 = x, p2 = x * x;
#pragma unroll
    for (int o = 16; o > 0; o >>= 1) {
        p1 += __shfl_down_sync(0xffffffffu, p1, o);
        p2 += __shfl_down_sync(0xffffffffu, p2, o);
    }
    int wix = d >> 5;
    if ((d & 31) == 0) { wsum[wix] = p1; wsq[wix] = p2; }
    __syncthreads();
    if (d == 0) {
        float ts = 0.f, tq = 0.f;
#pragma unroll
        for (int i = 0; i < 16; i++) { ts += wsum[i]; tq += wsq[i]; }
        float mean = ts * (1.f / HIDD);
        float var = tq * (1.f / HIDD) - mean * mean;
        red[0] = mean;
        red[1] = rsqrtf(var + LNEPS);
    }
    __syncthreads();
    float y = (x - red[0]) * red[1] * gamma[d] + beta[d];
    nodes[nrow * HIDD + d] = y;
    if (write_a) aout[nrow * HIDD + d] = __float2half_rn(y);
}

// ---------------- out = LN(nodes_row + y_row), single-pass (token rows) ----------------
__global__ void final_ln_kernel(const float* __restrict__ nodes,
                                int rpb, int bstride, int rbase,
                                const float* __restrict__ y,
                                const float* __restrict__ gamma,
                                const float* __restrict__ beta,
                                float* __restrict__ out) {
    int row = blockIdx.x;
    int tid = threadIdx.x;               // 256
    int pr = (row / rpb) * bstride + rbase + (row % rpb);
    size_t nb = (size_t)pr * HIDD;
    size_t yb = (size_t)row * HIDD;
    float x0 = nodes[nb + tid]       + y[yb + tid];
    float x1 = nodes[nb + tid + 256] + y[yb + tid + 256];
    __shared__ float wsum[8], wsq[8], mv[2];
    float s = x0 + x1;
    float s2 = x0 * x0 + x1 * x1;
#pragma unroll
    for (int o = 16; o > 0; o >>= 1) {
        s  += __shfl_down_sync(0xffffffffu, s,  o);
        s2 += __shfl_down_sync(0xffffffffu, s2, o);
    }
    int wix = tid >> 5;
    if ((tid & 31) == 0) { wsum[wix] = s; wsq[wix] = s2; }
    __syncthreads();
    if (tid == 0) {
        float ts = 0.f, tq = 0.f;
#pragma unroll
        for (int i = 0; i < 8; i++) { ts += wsum[i]; tq += wsq[i]; }
        float mean = ts * (1.f / HIDD);
        float var = tq * (1.f / HIDD) - mean * mean;
        mv[0] = mean;
        mv[1] = rsqrtf(var + LNEPS);
    }
    __syncthreads();
    float mean = mv[0], rstd = mv[1];
    out[yb + tid]       = (x0 - mean) * rstd * gamma[tid] + beta[tid];
    out[yb + tid + 256] = (x1 - mean) * rstd * gamma[tid + 256] + beta[tid + 256];
}

// ---------------- batched g/l final LN (32 blocks) ----------------
__global__ void gl_final_ln_kernel(const float* __restrict__ nodes,
                                   const float* __restrict__ ygl,
                                   const float* __restrict__ og,
                                   const float* __restrict__ ob,
                                   float* __restrict__ out_g,
                                   float* __restrict__ out_l) {
    int idx = blockIdx.x;
    int which = idx >> 4;
    int b = idx & 15;
    int tid = threadIdx.x;
    int qn = which == 0 ? 0 : NN - 1;
    const float* gamma = og + (which == 0 ? 0 : 2 * HIDD);
    const float* beta  = ob + (which == 0 ? 0 : 2 * HIDD);
    float* out = (which == 0 ? out_g : out_l) + (size_t)b * HIDD;
    size_t nb = ((size_t)b * NN + qn) * HIDD;
    size_t yb = ((size_t)which * BB + b) * HIDD;
    float x0 = nodes[nb + tid]       + ygl[yb + tid];
    float x1 = nodes[nb + tid + 256] + ygl[yb + tid + 256];
    __shared__ float wsum[8], wsq[8], mv[2];
    float s = x0 + x1;
    float s2 = x0 * x0 + x1 * x1;
#pragma unroll
    for (int o = 16; o > 0; o >>= 1) {
        s  += __shfl_down_sync(0xffffffffu, s,  o);
        s2 += __shfl_down_sync(0xffffffffu, s2, o);
    }
    int wix = tid >> 5;
    if ((tid & 31) == 0) { wsum[wix] = s; wsq[wix] = s2; }
    __syncthreads();
    if (tid == 0) {
        float ts = 0.f, tq = 0.f;
#pragma unroll
        for (int i = 0; i < 8; i++) { ts += wsum[i]; tq += wsq[i]; }
        float mean = ts * (1.f / HIDD);
        float var = tq * (1.f / HIDD) - mean * mean;
        mv[0] = mean;
        mv[1] = rsqrtf(var + LNEPS);
    }
    __syncthreads();
    float mean = mv[0], rstd = mv[1];
    out[tid]       = (x0 - mean) * rstd * gamma[tid] + beta[tid];
    out[tid + 256] = (x1 - mean) * rstd * gamma[tid + 256] + beta[tid + 256];
}

// ---------------- orchestration ----------------
extern "C" void kernel_launch(void* const* d_in, const int* in_sizes, int n_in,
                              void* d_out, int out_size) {
    const float* ge   = (const float*)d_in[0];
    const float* te   = (const float*)d_in[1];
    const float* le   = (const float*)d_in[2];
    const float* am   = (const float*)d_in[3];
    const int*   last = (const int*)  d_in[4];
    const float* W    = (const float*)d_in[5];
    const float* ga   = (const float*)d_in[6];
    const float* lng  = (const float*)d_in[7];
    const float* lnb  = (const float*)d_in[8];
    const float* w1   = (const float*)d_in[9];
    const float* b1   = (const float*)d_in[10];
    const float* w2   = (const float*)d_in[11];
    const float* b2   = (const float*)d_in[12];
    const float* og   = (const float*)d_in[13];
    const float* ob   = (const float*)d_in[14];
    float* out = (float*)d_out;

    float *nodes, *sqp, *skp, *ffn, *midgl, *ygl, *glpart;
    __half *proj, *Aproj, *Atok, *Amid, *Bw, *B1, *B2;
    cudaGetSymbolAddress((void**)&nodes, d_nodes);
    cudaGetSymbolAddress((void**)&sqp,   d_sq);
    cudaGetSymbolAddress((void**)&skp,   d_sk);
    cudaGetSymbolAddress((void**)&ffn,   d_ffn);
    cudaGetSymbolAddress((void**)&midgl, d_midgl);
    cudaGetSymbolAddress((void**)&ygl,   d_ygl);
    cudaGetSymbolAddress((void**)&glpart,d_glpart);
    cudaGetSymbolAddress((void**)&proj,  d_proj);
    cudaGetSymbolAddress((void**)&Aproj, d_Aproj);
    cudaGetSymbolAddress((void**)&Atok,  d_Atok);
    cudaGetSymbolAddress((void**)&Amid,  d_Amid);
    cudaGetSymbolAddress((void**)&Bw,    d_Bw);
    cudaGetSymbolAddress((void**)&B1,    d_B1);
    cudaGetSymbolAddress((void**)&B2,    d_B2);

    cudaFuncSetAttribute(mma_gemm_kernel,
                         cudaFuncAttributeMaxDynamicSharedMemorySize, GM_SMEM);

    const int MN = BB * NN;   // 16416
    const int MT = BB * LL;   // 16384

    build_nodes_kernel<<<(BB * NN * (HIDD / 4) + 255) / 256, 256>>>(ge, te, le, nodes, Aproj);

    castW_kernel<<<(NLAY * HIDD * HIDD / 4 + 255) / 256, 256>>>(W, Bw, NLAY * HIDD * HIDD / 4);
    splitT1_kernel<<<dim3(FF / 32, HIDD / 32), dim3(32, 8)>>>(w1 + (size_t)1 * HIDD * FF, B1, HIDD, FF);
    splitT1_kernel<<<dim3(HIDD / 32, FF / 32), dim3(32, 8)>>>(w2 + (size_t)1 * FF * HIDD, B2, FF, HIDD);

    for (int k = 0; k < NLAY; k++) {
        mma_gemm_kernel<<<dim3(NHEAD, (MN + 127) / 128), 256, GM_SMEM>>>(
            Aproj, Bw + (size_t)k * HIDD * HIDD, nullptr, nullptr, proj,
            MN, 8, HIDD, 0, 3, HIDD,
            ga + (size_t)k * NHEAD * 2 * DH, sqp, skp);
        gl_attn_part_kernel<<<dim3(2 * JSPLIT, BB), 512>>>(proj, sqp, skp, last, glpart);
        if (k == 0) {
            token_attn_ln_kernel<<<dim3(LL / QB, BB), 512>>>(
                proj, sqp, skp, am, last, nodes, lng, lnb, Aproj, 0);
            gl_ln_kernel<<<BB * 2, 512>>>(glpart, nodes, lng, lnb, Aproj, 1);
        } else {
            token_attn_ln_kernel<<<dim3(LL / QB, BB), 512>>>(
                proj, sqp, skp, am, last, nodes, lng + k * HIDD, lnb + k * HIDD, Atok, 1);
            gl_ln_kernel<<<BB * 2, 512>>>(glpart, nodes, lng + k * HIDD, lnb + k * HIDD,
                                          nullptr, 0);
        }
    }

    // token FFN
    mma_gemm_kernel<<<dim3(FF / 128, MT / 128), 256, GM_SMEM>>>(
        Atok, B1, b1 + 1 * FF, nullptr, Amid, MT, 8, HIDD, 0, 2, FF,
        nullptr, nullptr, nullptr);
    mma_gemm_kernel<<<dim3(HIDD / 128, MT / 128), 256, GM_SMEM>>>(
        Amid, B2, b2 + 1 * HIDD, ffn, nullptr, MT, 32, FF, HIDD, 1, 0,
        nullptr, nullptr, nullptr);
    final_ln_kernel<<<MT, 256>>>(nodes, LL, NN, 1, ffn,
                                 og + 1 * HIDD, ob + 1 * HIDD, out + BB * HIDD);

    // g/l FFN, batched over z
    sgemm_gl_kernel<<<dim3(FF / BN_, 1, 2), 256>>>(
        nodes, nodes,
        w1 + (size_t)0, w1 + (size_t)2 * HIDD * FF,
        b1 + 0, b1 + 2 * FF,
        midgl, midgl + (size_t)BB * FF,
        BB, FF, HIDD, /*gelu*/1, NN, 0, NN - 1);
    sgemm_gl_kernel<<<dim3(HIDD / BN_, 1, 2), 256>>>(
        midgl, midgl + (size_t)BB * FF,
        w2 + (size_t)0, w2 + (size_t)2 * FF * HIDD,
        b2 + 0, b2 + 2 * HIDD,
        ygl, ygl + (size_t)BB * HIDD,
        BB, HIDD, FF, 0, 1, 0, 0);
    gl_final_ln_kernel<<<2 * BB, 256>>>(nodes, ygl, og, ob,
                                        out,
                                        out + BB * HIDD + (size_t)BB * LL * HIDD);
}

// round 17
// speedup vs baseline: 1.1181x; 1.0145x over previous
#include <cuda_runtime.h>
#include <cuda_fp16.h>
#include <math.h>
#include <stdint.h>

// ---------------- problem constants ----------------
#define BB    16
#define LL    1024
#define NN    1026          // L + 2
#define HIDD  512
#define NHEAD 4
#define DH    128
#define NLAY  2
#define WINR  5
#define FF    2048          // 4*HID
#define SLOPE 0.2f
#define LNEPS 1e-5f
#define JSPLIT 4

// ---------------- scratch (device globals; no allocation allowed) ----------------
__device__ float d_nodes[(size_t)BB * NN * HIDD];
__device__ float d_sq   [(size_t)BB * NHEAD * NN];
__device__ float d_sk   [(size_t)BB * NHEAD * NN];
__device__ float d_ffn  [(size_t)BB * LL * HIDD];
__device__ float d_midgl[(size_t)2 * BB * FF];     // [g | l]
__device__ float d_ygl  [(size_t)2 * BB * HIDD];   // [g | l]
__device__ float d_glpart[(size_t)JSPLIT * BB * 2 * HIDD];

// fp16 buffers
__device__ __half d_proj [(size_t)(BB * NN) * HIDD];
__device__ __half d_Aproj[(size_t)(BB * NN) * HIDD];
__device__ __half d_Atok [(size_t)(BB * LL) * HIDD];
__device__ __half d_Amid [(size_t)(BB * LL) * FF];
__device__ __half d_Bw   [(size_t)NLAY * HIDD * HIDD];
__device__ __half d_B1   [(size_t)FF   * HIDD];
__device__ __half d_B2   [(size_t)HIDD * FF];

// ---------------- helpers ----------------
__device__ __forceinline__ float gelu_exact(float x) {
    return 0.5f * x * (1.0f + erff(x * 0.70710678118654752f));
}
__device__ __forceinline__ uint32_t smem_u32(const void* p) {
    uint32_t a;
    asm("{ .reg .u64 t; cvta.to.shared.u64 t, %1; cvt.u32.u64 %0, t; }" : "=r"(a) : "l"(p));
    return a;
}
__device__ __forceinline__ void cpa16(uint32_t dst, const void* src, bool pred) {
    int sz = pred ? 16 : 0;
    asm volatile("cp.async.cg.shared.global [%0], [%1], 16, %2;" :: "r"(dst), "l"(src), "r"(sz));
}
__device__ __forceinline__ void ldm_x4(uint32_t* r, uint32_t addr) {
    asm volatile("ldmatrix.sync.aligned.m8n8.x4.shared.b16 {%0, %1, %2, %3}, [%4];"
                 : "=r"(r[0]), "=r"(r[1]), "=r"(r[2]), "=r"(r[3]) : "r"(addr));
}
__device__ __forceinline__ void mma16816(float* d, const uint32_t* a, const uint32_t* b) {
    asm volatile("mma.sync.aligned.m16n8k16.row.col.f32.f16.f16.f32 "
                 "{%0, %1, %2, %3}, {%4, %5, %6, %7}, {%8, %9}, {%0, %1, %2, %3};"
                 : "+f"(d[0]), "+f"(d[1]), "+f"(d[2]), "+f"(d[3])
                 : "r"(a[0]), "r"(a[1]), "r"(a[2]), "r"(a[3]), "r"(b[0]), "r"(b[1]));
}
__device__ __forceinline__ uint32_t sw128(uint32_t off) {
    return off ^ ((off >> 3) & 0x70);
}

// ---------------- HMMA fp16 GEMM, 3-stage pipeline ----------------
// mode 0: Cf = acc ; mode 1: Cf = acc + bias ;
// mode 2: Cb[m*K0+n] = fp16(gelu(acc+bias))   (smem-staged coalesced store)
// mode 3: Cb[m*K0+n] = fp16(acc) + fused sq/sk emit (grid.x==NHEAD; staged store)
#define GM_SMEM (98304)
#define TILE_LD 136           // halves; 272B row stride, conflict-free
#define RED_OFF 40960         // byte offset of mode-3 reduce arrays (after 34.8KB tile)
__global__ void __launch_bounds__(256, 2)
mma_gemm_kernel(const __half* __restrict__ A,
                const __half* __restrict__ B,
                const float* __restrict__ bias,
                float* __restrict__ Cf,
                __half* __restrict__ Cb,
                int M, int Kt, int ldk, int ldc, int mode, int K0,
                const float* __restrict__ gq,
                float* __restrict__ sqo,
                float* __restrict__ sko) {
    extern __shared__ __align__(1024) char dynsm[];
    const uint32_t sbase = smem_u32(dynsm);
    const int tid  = threadIdx.x;
    const int lane = tid & 31;
    const int wid  = tid >> 5;
    const int wm   = wid & 1;
    const int wn   = wid >> 1;
    const int m0 = blockIdx.y * 128;
    const int n0 = blockIdx.x * 128;

    const char* Ag = (const char*)A;
    const char* Bg = (const char*)B;
    const size_t ldkb = (size_t)ldk * 2;

    float acc[4][4][4];
#pragma unroll
    for (int i = 0; i < 4; i++)
#pragma unroll
        for (int j = 0; j < 4; j++)
#pragma unroll
            for (int c = 0; c < 4; c++) acc[i][j][c] = 0.f;

    const int lrow[4] = { (0 * 256 + tid) >> 3, (1 * 256 + tid) >> 3,
                          (2 * 256 + tid) >> 3, (3 * 256 + tid) >> 3 };
    const int lch = tid & 7;

    auto load_tile = [&](int buf, int t) {
        size_t kb = (size_t)t * 128 + lch * 16;
        uint32_t sA = sbase + buf * 16384u;
        uint32_t sB = sbase + 49152u + buf * 16384u;
#pragma unroll
        for (int i = 0; i < 4; i++) {
            int row = lrow[i];
            uint32_t off = (uint32_t)(row * 128 + lch * 16);
            int m = m0 + row;
            cpa16(sA + sw128(off), Ag + (size_t)(m < M ? m : 0) * ldkb + kb, m < M);
        }
#pragma unroll
        for (int i = 0; i < 4; i++) {
            int row = lrow[i];
            uint32_t off = (uint32_t)(row * 128 + lch * 16);
            cpa16(sB + sw128(off), Bg + (size_t)(n0 + row) * ldkb + kb, true);
        }
        asm volatile("cp.async.commit_group;" ::: "memory");
    };

    auto compute_tile = [&](int buf) {
        uint32_t sA = sbase + buf * 16384u;
        uint32_t sB = sbase + 49152u + buf * 16384u;
        const int r15 = lane & 15;
        const int kh16 = (lane & 16);
#pragma unroll
        for (int ks = 0; ks < 4; ks++) {
            uint32_t kb = ks * 32 + kh16;
            uint32_t a[4][4];
#pragma unroll
            for (int tm = 0; tm < 4; tm++) {
                uint32_t off = (uint32_t)((wm * 64 + tm * 16 + r15) * 128) + kb;
                ldm_x4(a[tm], sA + sw128(off));
            }
            uint32_t b[4][2];
#pragma unroll
            for (int p = 0; p < 2; p++) {
                uint32_t r[4];
                uint32_t off = (uint32_t)((wn * 32 + p * 16 + r15) * 128) + kb;
                ldm_x4(r, sB + sw128(off));
                b[2 * p + 0][0] = r[0]; b[2 * p + 1][0] = r[1];
                b[2 * p + 0][1] = r[2]; b[2 * p + 1][1] = r[3];
            }
#pragma unroll
            for (int tm = 0; tm < 4; tm++)
#pragma unroll
                for (int tn = 0; tn < 4; tn++)
                    mma16816(acc[tm][tn], a[tm], b[tn]);
        }
    };

    load_tile(0, 0);
    load_tile(1, 1);
    int buf = 0;
    for (int t = 0; t < Kt; t++) {
        asm volatile("cp.async.wait_group 1;" ::: "memory");
        __syncthreads();
        if (t + 2 < Kt) {
            int nb = buf + 2; if (nb >= 3) nb -= 3;
            load_tile(nb, t + 2);
        } else {
            asm volatile("cp.async.commit_group;" ::: "memory");
        }
        compute_tile(buf);
        if (++buf == 3) buf = 0;
    }

    const int rbase = lane >> 2;
    const int cbase = 2 * (lane & 3);

    if (mode == 2 || mode == 3) {
        // ---- staged fp16 epilogue: smem tile -> coalesced global ----
        __half* tileh = (__half*)dynsm;
        float a1v[4][2], a2v[4][2];
        if (mode == 3) {
            const float* ah = gq + blockIdx.x * (2 * DH);
#pragma unroll
            for (int tn = 0; tn < 4; tn++) {
                int c0 = wn * 32 + tn * 8 + cbase;
                a1v[tn][0] = ah[c0];       a1v[tn][1] = ah[c0 + 1];
                a2v[tn][0] = ah[DH + c0];  a2v[tn][1] = ah[DH + c0 + 1];
            }
        }
        float p1[4][2], p2[4][2];
#pragma unroll
        for (int tm = 0; tm < 4; tm++) { p1[tm][0] = p1[tm][1] = p2[tm][0] = p2[tm][1] = 0.f; }

        __syncthreads();   // mainloop smem reads done; reuse as tile
#pragma unroll
        for (int tm = 0; tm < 4; tm++) {
#pragma unroll
            for (int half = 0; half < 2; half++) {
                int ml = wm * 64 + tm * 16 + rbase + half * 8;
#pragma unroll
                for (int tn = 0; tn < 4; tn++) {
                    int nl = wn * 32 + tn * 8 + cbase;
                    float v0 = acc[tm][tn][half * 2 + 0];
                    float v1 = acc[tm][tn][half * 2 + 1];
                    __half2 hv;
                    if (mode == 2) {
                        int n = n0 + nl;
                        hv.x = __float2half_rn(gelu_exact(v0 + bias[n]));
                        hv.y = __float2half_rn(gelu_exact(v1 + bias[n + 1]));
                    } else {
                        hv.x = __float2half_rn(v0);
                        hv.y = __float2half_rn(v1);
                        p1[tm][half] += v0 * a1v[tn][0] + v1 * a1v[tn][1];
                        p2[tm][half] += v0 * a2v[tn][0] + v1 * a2v[tn][1];
                    }
                    *(__half2*)&tileh[ml * TILE_LD + nl] = hv;
                }
            }
        }
        __syncthreads();
        // coalesced copy: 128 rows x 16 chunks of 16B
        for (int i = tid; i < 2048; i += 256) {
            int row = i >> 4, ch = i & 15;
            int m = m0 + row;
            if (m < M)
                *(uint4*)(Cb + (size_t)m * K0 + n0 + ch * 8) =
                    *(const uint4*)&tileh[row * TILE_LD + ch * 8];
        }

        if (mode == 3) {
            float* red1 = (float*)(dynsm + RED_OFF);
            float* red2 = red1 + 128 * 16;
            int slot = wn * 4 + (lane & 3);
#pragma unroll
            for (int tm = 0; tm < 4; tm++)
#pragma unroll
                for (int half = 0; half < 2; half++) {
                    int rb = wm * 64 + tm * 16 + rbase + half * 8;
                    red1[rb * 16 + slot] = p1[tm][half];
                    red2[rb * 16 + slot] = p2[tm][half];
                }
            __syncthreads();
            if (tid < 128) {
                int m = m0 + tid;
                if (m < M) {
                    float s1 = 0.f, s2 = 0.f;
#pragma unroll
                    for (int i = 0; i < 16; i++) {
                        s1 += red1[tid * 16 + i];
                        s2 += red2[tid * 16 + i];
                    }
                    int b = m / NN, n = m % NN;
                    size_t o = ((size_t)b * NHEAD + blockIdx.x) * NN + n;
                    sqo[o] = s1;
                    sko[o] = s2;
                }
            }
        }
    } else {
        // ---- fp32 epilogue (already 32B/row coalesced) ----
#pragma unroll
        for (int tm = 0; tm < 4; tm++) {
#pragma unroll
            for (int half = 0; half < 2; half++) {
                int m = m0 + wm * 64 + tm * 16 + rbase + half * 8;
                if (m >= M) continue;
#pragma unroll
                for (int tn = 0; tn < 4; tn++) {
                    int n = n0 + wn * 32 + tn * 8 + cbase;
                    float v0 = acc[tm][tn][half * 2 + 0];
                    float v1 = acc[tm][tn][half * 2 + 1];
                    if (mode == 1) { v0 += bias[n]; v1 += bias[n + 1]; }
                    float2 o; o.x = v0; o.y = v1;
                    *(float2*)(Cf + (size_t)m * ldc + n) = o;
                }
            }
        }
    }
}

// ---------------- weight conversion ----------------
__global__ void splitT1_kernel(const float* __restrict__ in,
                               __half* __restrict__ out,
                               int K, int N) {
    __shared__ float tile[32][33];
    int nb = blockIdx.x * 32;
    int kb = blockIdx.y * 32;
    int tx = threadIdx.x;
    int ty = threadIdx.y;
#pragma unroll
    for (int i = 0; i < 4; i++) {
        int k = kb + ty + i * 8;
        tile[ty + i * 8][tx] = in[(size_t)k * N + nb + tx];
    }
    __syncthreads();
#pragma unroll
    for (int i = 0; i < 4; i++) {
        int n = nb + ty + i * 8;
        out[(size_t)n * K + kb + tx] = __float2half_rn(tile[tx][ty + i * 8]);
    }
}
__global__ void castW_kernel(const float* __restrict__ in,
                             __half* __restrict__ out, int total4) {
    int idx = blockIdx.x * 256 + threadIdx.x;
    if (idx >= total4) return;
    float4 v = *(const float4*)(in + (size_t)idx * 4);
    __half2 h0, h1;
    h0.x = __float2half_rn(v.x); h0.y = __float2half_rn(v.y);
    h1.x = __float2half_rn(v.z); h1.y = __float2half_rn(v.w);
    *(__half2*)(out + (size_t)idx * 4)     = h0;
    *(__half2*)(out + (size_t)idx * 4 + 2) = h1;
}

// ---------------- build nodes (vectorized) ----------------
__global__ void build_nodes_kernel(const float* __restrict__ g,
                                   const float* __restrict__ t,
                                   const float* __restrict__ l,
                                   float* __restrict__ nodes,
                                   __half* __restrict__ aout) {
    int idx = blockIdx.x * 256 + threadIdx.x;
    int total4 = BB * NN * (HIDD / 4);
    if (idx >= total4) return;
    int d4 = (idx % (HIDD / 4)) * 4;
    int r = (idx / (HIDD / 4)) % NN;
    int b = idx / ((HIDD / 4) * NN);
    float4 v;
    if (r == 0)            v = *(const float4*)(g + (size_t)b * HIDD + d4);
    else if (r == NN - 1)  v = *(const float4*)(l + (size_t)b * HIDD + d4);
    else                   v = *(const float4*)(t + ((size_t)b * LL + (r - 1)) * HIDD + d4);
    size_t o = ((size_t)b * NN + r) * HIDD + d4;
    *(float4*)(nodes + o) = v;
    __half2 h0, h1;
    h0.x = __float2half_rn(v.x); h0.y = __float2half_rn(v.y);
    h1.x = __float2half_rn(v.z); h1.y = __float2half_rn(v.w);
    *(__half2*)(aout + o)     = h0;
    *(__half2*)(aout + o + 2) = h1;
}

// ---------------- batched g/l fp32 SGEMM ----------------
#define BM_ 64
#define BN_ 64
#define BK_ 16
__global__ void sgemm_gl_kernel(const float* __restrict__ A0,
                                const float* __restrict__ A1,
                                const float* __restrict__ B0,
                                const float* __restrict__ B1,
                                const float* __restrict__ bias0,
                                const float* __restrict__ bias1,
                                float* __restrict__ C0,
                                float* __restrict__ C1,
                                int M, int Ncol, int K, int act,
                                int astride, int arb0, int arb1) {
    const int z = blockIdx.z;
    const float* A   = z ? A1 : A0;
    const float* Bm  = z ? B1 : B0;
    const float* bias = z ? bias1 : bias0;
    float* C = z ? C1 : C0;
    const int arb = z ? arb1 : arb0;

    __shared__ float As[BM_][BK_];
    __shared__ float Bs[BK_][BN_];
    const int tid = threadIdx.x;
    const int tm = tid >> 4;
    const int tn = tid & 15;
    const int row0 = blockIdx.y * BM_;
    const int col0 = blockIdx.x * BN_;
    float acc[4][4] = {};
    const int ar = tid >> 2;
    const int ak = (tid & 3) << 2;
    const float* Arow = nullptr;
    {
        int mm = row0 + ar;
        if (mm < M) Arow = A + (size_t)(mm * astride + arb) * K;
    }
    const int bk0 = tid >> 4;
    const int bn0 = (tid & 15) << 2;
    for (int k0 = 0; k0 < K; k0 += BK_) {
        float4 av = make_float4(0.f, 0.f, 0.f, 0.f);
        if (Arow) av = *(const float4*)(Arow + k0 + ak);
        *(float4*)(&As[ar][ak]) = av;
        float4 bv = *(const float4*)(Bm + (size_t)(k0 + bk0) * Ncol + col0 + bn0);
        *(float4*)(&Bs[bk0][bn0]) = bv;
        __syncthreads();
#pragma unroll
        for (int kk = 0; kk < BK_; kk++) {
            float a0 = As[tm * 4 + 0][kk];
            float a1 = As[tm * 4 + 1][kk];
            float a2 = As[tm * 4 + 2][kk];
            float a3 = As[tm * 4 + 3][kk];
            float4 bv2 = *(const float4*)(&Bs[kk][tn * 4]);
            acc[0][0] += a0 * bv2.x; acc[0][1] += a0 * bv2.y; acc[0][2] += a0 * bv2.z; acc[0][3] += a0 * bv2.w;
            acc[1][0] += a1 * bv2.x; acc[1][1] += a1 * bv2.y; acc[1][2] += a1 * bv2.z; acc[1][3] += a1 * bv2.w;
            acc[2][0] += a2 * bv2.x; acc[2][1] += a2 * bv2.y; acc[2][2] += a2 * bv2.z; acc[2][3] += a2 * bv2.w;
            acc[3][0] += a3 * bv2.x; acc[3][1] += a3 * bv2.y; acc[3][2] += a3 * bv2.z; acc[3][3] += a3 * bv2.w;
        }
        __syncthreads();
    }
    int n = col0 + tn * 4;
    float4 bsv = make_float4(0.f, 0.f, 0.f, 0.f);
    if (bias) bsv = *(const float4*)(bias + n);
#pragma unroll
    for (int i = 0; i < 4; i++) {
        int mm = row0 + tm * 4 + i;
        if (mm >= M) continue;
        float4 v = make_float4(acc[i][0] + bsv.x, acc[i][1] + bsv.y,
                               acc[i][2] + bsv.z, acc[i][3] + bsv.w);
        if (act == 1) {
            v.x = gelu_exact(v.x); v.y = gelu_exact(v.y);
            v.z = gelu_exact(v.z); v.w = gelu_exact(v.w);
        }
        *(float4*)(C + (size_t)mm * Ncol + n) = v;
    }
}

// ---------------- fused token attention + elu + residual + LN + fp16 out ----------------
#define QB 8
#define UMAX 20
__global__ void __launch_bounds__(512)
token_attn_ln_kernel(const __half* __restrict__ P,
                     const float* __restrict__ sq,
                     const float* __restrict__ sk,
                     const float* __restrict__ am,
                     const int* __restrict__ last,
                     float* __restrict__ nodes,
                     const float* __restrict__ gamma,
                     const float* __restrict__ beta,
                     __half* __restrict__ aout,
                     int aidx_mode) {
    int b  = blockIdx.y;
    int i0 = blockIdx.x * QB;
    int tid = threadIdx.x;

    __shared__ __align__(16) float rows[UMAX][HIDD];
    __shared__ float sks[NHEAD][UMAX];
    __shared__ float w[QB][NHEAD][13];
    __shared__ int   qk[QB][13];
    __shared__ int   qnk[QB];
    __shared__ int   ukeys[UMAX];
    __shared__ int   unk_s;
    __shared__ float wsum[16], wsq[16];
    __shared__ float lnm[QB], lnr[QB];

    if (tid == 0) {
        int lo = i0 - WINR < 0 ? 0 : i0 - WINR;
        int hi = i0 + QB - 1 + WINR;
        if (hi > LL - 1) hi = LL - 1;
        int slot_t[2 * WINR + QB];
        int un = 0;
        ukeys[un++] = 0;
        for (int t = lo; t <= hi; t++) {
            if (am[b * LL + t] > 0.f) { ukeys[un] = 1 + t; slot_t[t - lo] = un; un++; }
            else slot_t[t - lo] = -1;
        }
        int lastv = last[b];
        int locslot = -1;
        if (i0 + QB - 1 >= lastv) { locslot = un; ukeys[un++] = NN - 1; }
        unk_s = un;
        for (int q = 0; q < QB; q++) {
            int i = i0 + q;
            int nk = 0;
            qk[q][nk++] = 0;
            int l2 = i - WINR < 0 ? 0 : i - WINR;
            int h2 = i + WINR > LL - 1 ? LL - 1 : i + WINR;
            for (int t = l2; t <= h2; t++) {
                int s = slot_t[t - lo];
                if (s >= 0) qk[q][nk++] = s;
            }
            if (i >= lastv) qk[q][nk++] = locslot;
            qnk[q] = nk;
        }
    }
    __syncthreads();
    int un = unk_s;

    {
        int rsub = tid >> 7;
        int d4 = (tid & 127) * 4;
        const __half* Pb = P + (size_t)b * NN * HIDD;
        for (int r = rsub; r < un; r += 4) {
            uint2 raw = *(const uint2*)(Pb + (size_t)ukeys[r] * HIDD + d4);
            __half2 h01 = *(__half2*)&raw.x;
            __half2 h23 = *(__half2*)&raw.y;
            float2 f01 = __half22float2(h01);
            float2 f23 = __half22float2(h23);
            rows[r][d4 + 0] = f01.x; rows[r][d4 + 1] = f01.y;
            rows[r][d4 + 2] = f23.x; rows[r][d4 + 3] = f23.y;
        }
    }
    if (tid < NHEAD * UMAX) {
        int h = tid / UMAX, kidx = tid % UMAX;
        if (kidx < un)
            sks[h][kidx] = sk[((size_t)b * NHEAD + h) * NN + ukeys[kidx]];
    }
    __syncthreads();

    if (tid < QB * NHEAD) {
        int q = tid >> 2, h = tid & 3;
        int nk = qnk[q];
        float sqv = sq[((size_t)b * NHEAD + h) * NN + 1 + i0 + q];
        float sc[13];
        float mx = -3e38f;
        for (int jj = 0; jj < nk; jj++) {
            float s = sqv + sks[h][qk[q][jj]];
            s = s >= 0.f ? s : SLOPE * s;
            sc[jj] = s;
            mx = fmaxf(mx, s);
        }
        float sum = 0.f;
        for (int jj = 0; jj < nk; jj++) {
            float e = expf(sc[jj] - mx);
            w[q][h][jj] = e;
            sum += e;
        }
        float inv = 1.f / sum;
        for (int jj = 0; jj < nk; jj++) w[q][h][jj] *= inv;
    }
    __syncthreads();

    int d = tid;
    int h = d >> 7;
    float v[QB];
#pragma unroll
    for (int q = 0; q < QB; q++) {
        int nk = qnk[q];
        float acc = 0.f;
        for (int jj = 0; jj < nk; jj++)
            acc += w[q][h][jj] * rows[qk[q][jj]][d];
        acc = acc > 0.f ? acc : expm1f(acc);
        v[q] = acc + nodes[((size_t)b * NN + 1 + i0 + q) * HIDD + d];
    }
    __syncthreads();

#pragma unroll
    for (int q = 0; q < QB; q++) rows[q][d] = v[q];
    __syncthreads();

    {
        int g = tid >> 6;
        int t = tid & 63;
        float s = 0.f, s2 = 0.f;
#pragma unroll
        for (int j = 0; j < 8; j++) {
            float x = rows[g][t + 64 * j];
            s += x; s2 += x * x;
        }
#pragma unroll
        for (int o = 16; o > 0; o >>= 1) {
            s  += __shfl_down_sync(0xffffffffu, s,  o);
            s2 += __shfl_down_sync(0xffffffffu, s2, o);
        }
        int wix = tid >> 5;
        if ((tid & 31) == 0) { wsum[wix] = s; wsq[wix] = s2; }
        __syncthreads();
        if (t == 0) {
            float ts = wsum[2 * g] + wsum[2 * g + 1];
            float tq = wsq[2 * g] + wsq[2 * g + 1];
            float mean = ts * (1.f / HIDD);
            float var = tq * (1.f / HIDD) - mean * mean;
            lnm[g] = mean;
            lnr[g] = rsqrtf(var + LNEPS);
        }
        __syncthreads();
    }

    float gmv = gamma[d], btv = beta[d];
#pragma unroll
    for (int q = 0; q < QB; q++) {
        float y = (v[q] - lnm[q]) * lnr[q] * gmv + btv;
        nodes[((size_t)b * NN + 1 + i0 + q) * HIDD + d] = y;
        size_t orow = (aidx_mode == 0) ? ((size_t)b * NN + 1 + i0 + q)
                                       : ((size_t)b * LL + i0 + q);
        aout[orow * HIDD + d] = __float2half_rn(y);
    }
}

// ---------------- dense global/local attention, J-split partials ----------------
// PV phase: 256 threads own d-pairs (half2 loads), 2-way j split.
__global__ void __launch_bounds__(512)
gl_attn_part_kernel(const __half* __restrict__ P,
                    const float* __restrict__ sq,
                    const float* __restrict__ sk,
                    const int* __restrict__ last,
                    float* __restrict__ part) {
    int b = blockIdx.y;
    int which = blockIdx.x & 1;
    int js = blockIdx.x >> 1;
    int qn = which == 0 ? 0 : NN - 1;
    int tid = threadIdx.x;
    __shared__ float ssm[NHEAD][NN];
    __shared__ float red[512];
    __shared__ float2 pvbuf[2][256];
    int lastv = last[b];
    int h = tid >> 7;
    int r = tid & 127;
    float sqv = sq[((size_t)b * NHEAD + h) * NN + qn];
    const float* skh = sk + ((size_t)b * NHEAD + h) * NN;
    float mx = -3e38f;
    for (int j = r; j < NN; j += 128) {
        bool ok = (which == 0) || (j == 0) || (j == NN - 1) ||
                  (j >= lastv + 1 && j <= LL);
        float s;
        if (ok) {
            s = sqv + skh[j];
            s = s >= 0.f ? s : SLOPE * s;
        } else s = -1e30f;
        ssm[h][j] = s;
        mx = fmaxf(mx, s);
    }
    red[tid] = mx;
    __syncthreads();
    for (int s = 64; s > 0; s >>= 1) {
        if (r < s) red[tid] = fmaxf(red[tid], red[tid + s]);
        __syncthreads();
    }
    float mhead = red[h * 128];
    __syncthreads();
    float sum = 0.f;
    for (int j = r; j < NN; j += 128) {
        float e = expf(ssm[h][j] - mhead);
        ssm[h][j] = e;
        sum += e;
    }
    red[tid] = sum;
    __syncthreads();
    for (int s = 64; s > 0; s >>= 1) {
        if (r < s) red[tid] += red[tid + s];
        __syncthreads();
    }
    float inv = 1.f / red[h * 128];
    __syncthreads();
    for (int j = r; j < NN; j += 128) ssm[h][j] *= inv;
    __syncthreads();

    const int CH = (NN + JSPLIT - 1) / JSPLIT;
    int jlo = js * CH;
    int jhi = jlo + CH; if (jhi > NN) jhi = NN;

    int dp = tid & 255;
    int jh = tid >> 8;
    int hh = dp >> 6;
    const __half2* Pb2 = (const __half2*)(P + (size_t)b * NN * HIDD) + dp;
    float2 accA = make_float2(0.f, 0.f);
    float2 accB = make_float2(0.f, 0.f);
    int j = jlo + jh;
    for (; j + 6 < jhi; j += 8) {
        float2 q0 = __half22float2(Pb2[(size_t)(j + 0) * 256]);
        float2 q1 = __half22float2(Pb2[(size_t)(j + 2) * 256]);
        float2 q2 = __half22float2(Pb2[(size_t)(j + 4) * 256]);
        float2 q3 = __half22float2(Pb2[(size_t)(j + 6) * 256]);
        float w0 = ssm[hh][j + 0], w1 = ssm[hh][j + 2];
        float w2 = ssm[hh][j + 4], w3 = ssm[hh][j + 6];
        accA.x += w0 * q0.x + w1 * q1.x;
        accA.y += w0 * q0.y + w1 * q1.y;
        accB.x += w2 * q2.x + w3 * q3.x;
        accB.y += w2 * q2.y + w3 * q3.y;
    }
    for (; j < jhi; j += 2) {
        float2 q = __half22float2(Pb2[(size_t)j * 256]);
        float wv = ssm[hh][j];
        accA.x += wv * q.x;
        accA.y += wv * q.y;
    }
    pvbuf[jh][dp] = make_float2(accA.x + accB.x, accA.y + accB.y);
    __syncthreads();
    if (tid < 256) {
        float2 a = pvbuf[0][tid];
        float2 c = pvbuf[1][tid];
        float2 o = make_float2(a.x + c.x, a.y + c.y);
        *(float2*)(&part[(((size_t)js * BB + b) * 2 + which) * HIDD + 2 * tid]) = o;
    }
}

// ---------------- fused gl reduce + elu + residual + LN + optional fp16 out ----------------
__global__ void __launch_bounds__(512)
gl_ln_kernel(const float* __restrict__ part,
             float* __restrict__ nodes,
             const float* __restrict__ gamma,
             const float* __restrict__ beta,
             __half* __restrict__ aout,
             int write_a) {
    int row = blockIdx.x;
    int b = row >> 1;
    int which = row & 1;
    int qn = which == 0 ? 0 : NN - 1;
    int d = threadIdx.x;
    float s = 0.f;
#pragma unroll
    for (int js = 0; js < JSPLIT; js++)
        s += part[(((size_t)js * BB + b) * 2 + which) * HIDD + d];
    s = s > 0.f ? s : expm1f(s);
    size_t nrow = (size_t)b * NN + qn;
    float x = nodes[nrow * HIDD + d] + s;

    __shared__ float red[2];
    __shared__ float wsum[16], wsq[16];
    float p1 = x, p2 = x * x;
#pragma unroll
    for (int o = 16; o > 0; o >>= 1) {
        p1 += __shfl_down_sync(0xffffffffu, p1, o);
        p2 += __shfl_down_sync(0xffffffffu, p2, o);
    }
    int wix = d >> 5;
    if ((d & 31) == 0) { wsum[wix] = p1; wsq[wix] = p2; }
    __syncthreads();
    if (d == 0) {
        float ts = 0.f, tq = 0.f;
#pragma unroll
        for (int i = 0; i < 16; i++) { ts += wsum[i]; tq += wsq[i]; }
        float mean = ts * (1.f / HIDD);
        float var = tq * (1.f / HIDD) - mean * mean;
        red[0] = mean;
        red[1] = rsqrtf(var + LNEPS);
    }
    __syncthreads();
    float y = (x - red[0]) * red[1] * gamma[d] + beta[d];
    nodes[nrow * HIDD + d] = y;
    if (write_a) aout[nrow * HIDD + d] = __float2half_rn(y);
}

// ---------------- out = LN(nodes_row + y_row), single-pass (token rows) ----------------
__global__ void final_ln_kernel(const float* __restrict__ nodes,
                                int rpb, int bstride, int rbase,
                                const float* __restrict__ y,
                                const float* __restrict__ gamma,
                                const float* __restrict__ beta,
                                float* __restrict__ out) {
    int row = blockIdx.x;
    int tid = threadIdx.x;               // 256
    int pr = (row / rpb) * bstride + rbase + (row % rpb);
    size_t nb = (size_t)pr * HIDD;
    size_t yb = (size_t)row * HIDD;
    float x0 = nodes[nb + tid]       + y[yb + tid];
    float x1 = nodes[nb + tid + 256] + y[yb + tid + 256];
    __shared__ float wsum[8], wsq[8], mv[2];
    float s = x0 + x1;
    float s2 = x0 * x0 + x1 * x1;
#pragma unroll
    for (int o = 16; o > 0; o >>= 1) {
        s  += __shfl_down_sync(0xffffffffu, s,  o);
        s2 += __shfl_down_sync(0xffffffffu, s2, o);
    }
    int wix = tid >> 5;
    if ((tid & 31) == 0) { wsum[wix] = s; wsq[wix] = s2; }
    __syncthreads();
    if (tid == 0) {
        float ts = 0.f, tq = 0.f;
#pragma unroll
        for (int i = 0; i < 8; i++) { ts += wsum[i]; tq += wsq[i]; }
        float mean = ts * (1.f / HIDD);
        float var = tq * (1.f / HIDD) - mean * mean;
        mv[0] = mean;
        mv[1] = rsqrtf(var + LNEPS);
    }
    __syncthreads();
    float mean = mv[0], rstd = mv[1];
    out[yb + tid]       = (x0 - mean) * rstd * gamma[tid] + beta[tid];
    out[yb + tid + 256] = (x1 - mean) * rstd * gamma[tid + 256] + beta[tid + 256];
}

// ---------------- batched g/l final LN (32 blocks) ----------------
__global__ void gl_final_ln_kernel(const float* __restrict__ nodes,
                                   const float* __restrict__ ygl,
                                   const float* __restrict__ og,
                                   const float* __restrict__ ob,
                                   float* __restrict__ out_g,
                                   float* __restrict__ out_l) {
    int idx = blockIdx.x;
    int which = idx >> 4;
    int b = idx & 15;
    int tid = threadIdx.x;
    int qn = which == 0 ? 0 : NN - 1;
    const float* gamma = og + (which == 0 ? 0 : 2 * HIDD);
    const float* beta  = ob + (which == 0 ? 0 : 2 * HIDD);
    float* out = (which == 0 ? out_g : out_l) + (size_t)b * HIDD;
    size_t nb = ((size_t)b * NN + qn) * HIDD;
    size_t yb = ((size_t)which * BB + b) * HIDD;
    float x0 = nodes[nb + tid]       + ygl[yb + tid];
    float x1 = nodes[nb + tid + 256] + ygl[yb + tid + 256];
    __shared__ float wsum[8], wsq[8], mv[2];
    float s = x0 + x1;
    float s2 = x0 * x0 + x1 * x1;
#pragma unroll
    for (int o = 16; o > 0; o >>= 1) {
        s  += __shfl_down_sync(0xffffffffu, s,  o);
        s2 += __shfl_down_sync(0xffffffffu, s2, o);
    }
    int wix = tid >> 5;
    if ((tid & 31) == 0) { wsum[wix] = s; wsq[wix] = s2; }
    __syncthreads();
    if (tid == 0) {
        float ts = 0.f, tq = 0.f;
#pragma unroll
        for (int i = 0; i < 8; i++) { ts += wsum[i]; tq += wsq[i]; }
        float mean = ts * (1.f / HIDD);
        float var = tq * (1.f / HIDD) - mean * mean;
        mv[0] = mean;
        mv[1] = rsqrtf(var + LNEPS);
    }
    __syncthreads();
    float mean = mv[0], rstd = mv[1];
    out[tid]       = (x0 - mean) * rstd * gamma[tid] + beta[tid];
    out[tid + 256] = (x1 - mean) * rstd * gamma[tid + 256] + beta[tid + 256];
}

// ---------------- orchestration ----------------
extern "C" void kernel_launch(void* const* d_in, const int* in_sizes, int n_in,
                              void* d_out, int out_size) {
    const float* ge   = (const float*)d_in[0];
    const float* te   = (const float*)d_in[1];
    const float* le   = (const float*)d_in[2];
    const float* am   = (const float*)d_in[3];
    const int*   last = (const int*)  d_in[4];
    const float* W    = (const float*)d_in[5];
    const float* ga   = (const float*)d_in[6];
    const float* lng  = (const float*)d_in[7];
    const float* lnb  = (const float*)d_in[8];
    const float* w1   = (const float*)d_in[9];
    const float* b1   = (const float*)d_in[10];
    const float* w2   = (const float*)d_in[11];
    const float* b2   = (const float*)d_in[12];
    const float* og   = (const float*)d_in[13];
    const float* ob   = (const float*)d_in[14];
    float* out = (float*)d_out;

    float *nodes, *sqp, *skp, *ffn, *midgl, *ygl, *glpart;
    __half *proj, *Aproj, *Atok, *Amid, *Bw, *B1, *B2;
    cudaGetSymbolAddress((void**)&nodes, d_nodes);
    cudaGetSymbolAddress((void**)&sqp,   d_sq);
    cudaGetSymbolAddress((void**)&skp,   d_sk);
    cudaGetSymbolAddress((void**)&ffn,   d_ffn);
    cudaGetSymbolAddress((void**)&midgl, d_midgl);
    cudaGetSymbolAddress((void**)&ygl,   d_ygl);
    cudaGetSymbolAddress((void**)&glpart,d_glpart);
    cudaGetSymbolAddress((void**)&proj,  d_proj);
    cudaGetSymbolAddress((void**)&Aproj, d_Aproj);
    cudaGetSymbolAddress((void**)&Atok,  d_Atok);
    cudaGetSymbolAddress((void**)&Amid,  d_Amid);
    cudaGetSymbolAddress((void**)&Bw,    d_Bw);
    cudaGetSymbolAddress((void**)&B1,    d_B1);
    cudaGetSymbolAddress((void**)&B2,    d_B2);

    cudaFuncSetAttribute(mma_gemm_kernel,
                         cudaFuncAttributeMaxDynamicSharedMemorySize, GM_SMEM);

    const int MN = BB * NN;   // 16416
    const int MT = BB * LL;   // 16384

    build_nodes_kernel<<<(BB * NN * (HIDD / 4) + 255) / 256, 256>>>(ge, te, le, nodes, Aproj);

    castW_kernel<<<(NLAY * HIDD * HIDD / 4 + 255) / 256, 256>>>(W, Bw, NLAY * HIDD * HIDD / 4);
    splitT1_kernel<<<dim3(FF / 32, HIDD / 32), dim3(32, 8)>>>(w1 + (size_t)1 * HIDD * FF, B1, HIDD, FF);
    splitT1_kernel<<<dim3(HIDD / 32, FF / 32), dim3(32, 8)>>>(w2 + (size_t)1 * FF * HIDD, B2, FF, HIDD);

    for (int k = 0; k < NLAY; k++) {
        mma_gemm_kernel<<<dim3(NHEAD, (MN + 127) / 128), 256, GM_SMEM>>>(
            Aproj, Bw + (size_t)k * HIDD * HIDD, nullptr, nullptr, proj,
            MN, 8, HIDD, 0, 3, HIDD,
            ga + (size_t)k * NHEAD * 2 * DH, sqp, skp);
        gl_attn_part_kernel<<<dim3(2 * JSPLIT, BB), 512>>>(proj, sqp, skp, last, glpart);
        if (k == 0) {
            token_attn_ln_kernel<<<dim3(LL / QB, BB), 512>>>(
                proj, sqp, skp, am, last, nodes, lng, lnb, Aproj, 0);
            gl_ln_kernel<<<BB * 2, 512>>>(glpart, nodes, lng, lnb, Aproj, 1);
        } else {
            token_attn_ln_kernel<<<dim3(LL / QB, BB), 512>>>(
                proj, sqp, skp, am, last, nodes, lng + k * HIDD, lnb + k * HIDD, Atok, 1);
            gl_ln_kernel<<<BB * 2, 512>>>(glpart, nodes, lng + k * HIDD, lnb + k * HIDD,
                                          nullptr, 0);
        }
    }

    // token FFN
    mma_gemm_kernel<<<dim3(FF / 128, MT / 128), 256, GM_SMEM>>>(
        Atok, B1, b1 + 1 * FF, nullptr, Amid, MT, 8, HIDD, 0, 2, FF,
        nullptr, nullptr, nullptr);
    mma_gemm_kernel<<<dim3(HIDD / 128, MT / 128), 256, GM_SMEM>>>(
        Amid, B2, b2 + 1 * HIDD, ffn, nullptr, MT, 32, FF, HIDD, 1, 0,
        nullptr, nullptr, nullptr);
    final_ln_kernel<<<MT, 256>>>(nodes, LL, NN, 1, ffn,
                                 og + 1 * HIDD, ob + 1 * HIDD, out + BB * HIDD);

    // g/l FFN, batched over z
    sgemm_gl_kernel<<<dim3(FF / BN_, 1, 2), 256>>>(
        nodes, nodes,
        w1 + (size_t)0, w1 + (size_t)2 * HIDD * FF,
        b1 + 0, b1 + 2 * FF,
        midgl, midgl + (size_t)BB * FF,
        BB, FF, HIDD, /*gelu*/1, NN, 0, NN - 1);
    sgemm_gl_kernel<<<dim3(HIDD / BN_, 1, 2), 256>>>(
        midgl, midgl + (size_t)BB * FF,
        w2 + (size_t)0, w2 + (size_t)2 * FF * HIDD,
        b2 + 0, b2 + 2 * HIDD,
        ygl, ygl + (size_t)BB * HIDD,
        BB, HIDD, FF, 0, 1, 0, 0);
    gl_final_ln_kernel<<<2 * BB, 256>>>(nodes, ygl, og, ob,
                                        out,
                                        out + BB * HIDD + (size_t)BB * LL * HIDD);
}